// round 3
// baseline (speedup 1.0000x reference)
#include <cuda_runtime.h>
#include <math.h>

#define NNODES 20000
#define NEDGES 320000
#define HD 128

// ---------------- scratch (static device allocations) ----------------
__device__ int   g_is64;
__device__ __align__(16) float g_deg[NNODES];
__device__ __align__(16) float g_dis[NNODES];
__device__ __align__(16) int   g_src[NEDGES];
__device__ __align__(16) int   g_dst[NEDGES];
__device__ __align__(16) float g_norm[NEDGES];
__device__ __align__(16) float g_ax[(size_t)NNODES * HD];   // prop(x)
__device__ __align__(16) float g_ah[(size_t)NNODES * HD];   // prop(h)
__device__ __align__(16) float g_z[(size_t)NNODES * 1024];  // relu layer-1: [N][x gates | h gates]
__device__ __align__(16) float g_y[(size_t)NNODES * 512];   // pre-prop gate features
__device__ __align__(16) float g_G[(size_t)NNODES * 512];   // post-prop gate features

// ---------------- dtype detection for edge_index (int32 vs int64) ----------------
// If int64 (little-endian), int32 words at odd positions are high words of
// indices < 20000 -> all zero. If int32, they are random indices, mostly nonzero.
__global__ void k_detect(const int* __restrict__ ei32) {
    __shared__ int nz;
    if (threadIdx.x == 0) nz = 0;
    __syncthreads();
    int v = ei32[2 * threadIdx.x + 1];
    if (v != 0) atomicAdd(&nz, 1);
    __syncthreads();
    if (threadIdx.x == 0) g_is64 = (nz == 0) ? 1 : 0;
}

// ---------------- degree / norm ----------------
__global__ void k_init_deg() {
    int i = blockIdx.x * blockDim.x + threadIdx.x;
    if (i < NNODES) g_deg[i] = 1.0f;  // self-loop weight
}

__global__ void k_edge_prep(const void* __restrict__ ei_raw,
                            const float* __restrict__ w) {
    int e = blockIdx.x * blockDim.x + threadIdx.x;
    if (e >= NEDGES) return;
    int s, d;
    if (g_is64) {
        const long long* ei = (const long long*)ei_raw;
        s = (int)ei[e];
        d = (int)ei[NEDGES + e];
    } else {
        const int* ei = (const int*)ei_raw;
        s = ei[e];
        d = ei[NEDGES + e];
    }
    if ((unsigned)s >= NNODES || (unsigned)d >= NNODES) { g_src[e] = 0; g_dst[e] = 0; g_norm[e] = 0.f; return; }
    g_src[e] = s;
    g_dst[e] = d;
    atomicAdd(&g_deg[d], w[e]);
}

__global__ void k_dis() {
    int i = blockIdx.x * blockDim.x + threadIdx.x;
    if (i < NNODES) {
        float dg = g_deg[i];
        g_dis[i] = dg > 0.f ? rsqrtf(fmaxf(dg, 1e-12f)) : 0.f;
    }
}

__global__ void k_norm(const float* __restrict__ w) {
    int e = blockIdx.x * blockDim.x + threadIdx.x;
    if (e < NEDGES) {
        g_norm[e] = g_dis[g_src[e]] * w[e] * g_dis[g_dst[e]];
    }
}

// ---------------- SpMM: out = D^-1/2 (A+I) D^-1/2 in ----------------
// WHICH: 0 -> in=ext, out=g_ax ; 1 -> in=ext, out=g_ah ; 2 -> in=g_y, out=g_G
template<int F, int WHICH>
__global__ void k_spmm_init(const float* __restrict__ ext) {
    const float* in = (WHICH == 2) ? g_y : ext;
    float* out = (WHICH == 0) ? g_ax : (WHICH == 1) ? g_ah : g_G;
    int idx = blockIdx.x * blockDim.x + threadIdx.x;   // over N*F/4
    if (idx >= NNODES * (F / 4)) return;
    int i = idx / (F / 4);
    float s = g_dis[i];
    s = s * s;                                          // self-loop: dis[i]*1*dis[i]
    float4 v = ((const float4*)in)[idx];
    v.x *= s; v.y *= s; v.z *= s; v.w *= s;
    ((float4*)out)[idx] = v;
}

template<int F, int WHICH>
__global__ void k_spmm_edges(const float* __restrict__ ext) {
    const float* in = (WHICH == 2) ? g_y : ext;
    float* out = (WHICH == 0) ? g_ax : (WHICH == 1) ? g_ah : g_G;
    const int QC = F / 4;
    int idx = blockIdx.x * blockDim.x + threadIdx.x;    // over E*QC (max 40.96M, fits int)
    if (idx >= NEDGES * QC) return;
    int e = idx / QC;
    int q = idx - e * QC;
    int s = g_src[e];
    int d = g_dst[e];
    float nrm = g_norm[e];
    float4 v = *(const float4*)(in + (size_t)s * F + q * 4);
    float* o = out + (size_t)d * F + q * 4;
    atomicAdd(o + 0, nrm * v.x);
    atomicAdd(o + 1, nrm * v.y);
    atomicAdd(o + 2, nrm * v.z);
    atomicAdd(o + 3, nrm * v.w);
}

// ---------------- tiled SGEMM: C = act(sum_s A_s[M,128] @ B_s[128,128] + bias) ----------------
// BM=64, BN=128, BK=16, 256 threads, 4x8 microtile per thread.
template<int NS, bool RELU>
__device__ __forceinline__ void gemm_tile(
    const float* A0, const float* A1, int lda,
    const float* B0, const float* B1,
    const float* bias, float* C, int ldc)
{
    __shared__ float As[16][68];    // [k][row], padded
    __shared__ float Bs[16][128];   // [k][col]

    int tid = threadIdx.x;
    int tcx = tid & 15;     // 16 col groups of 8
    int trx = tid >> 4;     // 16 row groups of 4
    int row0 = blockIdx.x * 64;

    float acc[4][8];
#pragma unroll
    for (int m = 0; m < 4; m++)
#pragma unroll
        for (int n = 0; n < 8; n++) acc[m][n] = 0.f;

    int lq = tid & 3;       // which float4 along k in A row
    int lr = tid >> 2;      // A row 0..63
    int bi = tid >> 5;      // B row base 0..7
    int bc = tid & 31;      // B col quad

#pragma unroll
    for (int s = 0; s < NS; ++s) {
        const float* A = (s == 0) ? A0 : A1;
        const float* B = (s == 0) ? B0 : B1;
        for (int k0 = 0; k0 < 128; k0 += 16) {
            __syncthreads();
            // load A tile (64 x 16), guarded
            float4 av = make_float4(0.f, 0.f, 0.f, 0.f);
            int grow = row0 + lr;
            if (grow < NNODES)
                av = *(const float4*)(A + (size_t)grow * lda + k0 + 4 * lq);
            As[4 * lq + 0][lr] = av.x;
            As[4 * lq + 1][lr] = av.y;
            As[4 * lq + 2][lr] = av.z;
            As[4 * lq + 3][lr] = av.w;
            // load B tile (16 x 128), row-major ldb=128
            *(float4*)&Bs[bi][bc * 4]     = *(const float4*)(B + (k0 + bi) * 128 + bc * 4);
            *(float4*)&Bs[bi + 8][bc * 4] = *(const float4*)(B + (k0 + bi + 8) * 128 + bc * 4);
            __syncthreads();
#pragma unroll
            for (int k = 0; k < 16; k++) {
                float a[4];
#pragma unroll
                for (int m = 0; m < 4; m++) a[m] = As[k][trx * 4 + m];
                float4 b0 = *(float4*)&Bs[k][tcx * 8];
                float4 b1 = *(float4*)&Bs[k][tcx * 8 + 4];
                float bb[8] = {b0.x, b0.y, b0.z, b0.w, b1.x, b1.y, b1.z, b1.w};
#pragma unroll
                for (int m = 0; m < 4; m++)
#pragma unroll
                    for (int n = 0; n < 8; n++)
                        acc[m][n] = fmaf(a[m], bb[n], acc[m][n]);
            }
        }
    }
    // epilogue
#pragma unroll
    for (int m = 0; m < 4; m++) {
        int grow = row0 + trx * 4 + m;
        if (grow >= NNODES) continue;
#pragma unroll
        for (int n = 0; n < 8; n++) {
            int col = tcx * 8 + n;
            float v = acc[m][n];
            if (bias) v += bias[col];
            if (RELU) v = fmaxf(v, 0.f);
            C[(size_t)grow * ldc + col] = v;
        }
    }
}

// layer 1: z[:, sg*128 .. +128] = relu(a_s @ W0_s[g] + b0_s[g]),  sg = s*4+g
__global__ void k_gemm1(const float* __restrict__ Wx0, const float* __restrict__ Wh0,
                        const float* __restrict__ bx0, const float* __restrict__ bh0) {
    int sg = blockIdx.y;
    int s = sg >> 2, g = sg & 3;
    const float* A    = s ? g_ah : g_ax;
    const float* W    = (s ? Wh0 : Wx0) + g * 128 * 128;
    const float* bias = (s ? bh0 : bx0) + g * 128;
    gemm_tile<1, true>(A, nullptr, 128, W, nullptr, bias, g_z + sg * 128, 1024);
}

// layer 2 (pre-prop, NO bias): y[:, g*128..] = z_x[g] @ Wx1[g] + z_h[g] @ Wh1[g]
__global__ void k_gemm2(const float* __restrict__ Wx1, const float* __restrict__ Wh1) {
    int g = blockIdx.y;
    gemm_tile<2, false>(g_z + g * 128, g_z + 512 + g * 128, 1024,
                        Wx1 + g * 128 * 128, Wh1 + g * 128 * 128,
                        nullptr, g_y + g * 128, 512);
}

// ---------------- LSTM gates (adds deferred layer-2 biases) ----------------
__device__ __forceinline__ float sigmoidf_(float v) { return 1.f / (1.f + expf(-v)); }

__global__ void k_lstm(const float* __restrict__ c,
                       const float* __restrict__ bx1, const float* __restrict__ bh1,
                       const float* __restrict__ wc, const float* __restrict__ bg,
                       float* __restrict__ out) {
    int idx = blockIdx.x * blockDim.x + threadIdx.x;
    if (idx >= NNODES * HD) return;
    int n = idx >> 7, f = idx & 127;
    const float* Gn = g_G + (size_t)n * 512;
    float cv = c[idx];
    float Gi = Gn[f]       + bx1[f]       + bh1[f];
    float Gf = Gn[128 + f] + bx1[128 + f] + bh1[128 + f];
    float Gc = Gn[256 + f] + bx1[256 + f] + bh1[256 + f];
    float Go = Gn[384 + f] + bx1[384 + f] + bh1[384 + f];
    float I  = sigmoidf_(Gi + wc[f] * cv + bg[f]);
    float Fg = sigmoidf_(Gf + wc[128 + f] * cv + bg[128 + f]);
    float T  = tanhf(Gc + bg[256 + f]);
    float Cn = Fg * cv + I * T;
    float O  = sigmoidf_(Go + wc[256 + f] * Cn + bg[384 + f]);
    float Hn = O * tanhf(Cn);
    out[idx] = Hn;
    out[(size_t)NNODES * HD + idx] = Cn;
}

// ---------------- launch ----------------
extern "C" void kernel_launch(void* const* d_in, const int* in_sizes, int n_in,
                              void* d_out, int out_size) {
    const float* x   = (const float*)d_in[0];
    const void*  ei  = d_in[1];                 // int32 or int64, detected on device
    const float* w   = (const float*)d_in[2];
    const float* h   = (const float*)d_in[3];
    const float* c   = (const float*)d_in[4];
    const float* Wx0 = (const float*)d_in[5];
    const float* bx0 = (const float*)d_in[6];
    const float* Wx1 = (const float*)d_in[7];
    const float* bx1 = (const float*)d_in[8];
    const float* Wh0 = (const float*)d_in[9];
    const float* bh0 = (const float*)d_in[10];
    const float* Wh1 = (const float*)d_in[11];
    const float* bh1 = (const float*)d_in[12];
    const float* wc  = (const float*)d_in[13];
    const float* bg  = (const float*)d_in[14];
    float* out = (float*)d_out;

    const int T = 256;
    // edge_index dtype detection + norm precompute
    k_detect<<<1, 128>>>((const int*)ei);
    k_init_deg<<<(NNODES + T - 1) / T, T>>>();
    k_edge_prep<<<(NEDGES + T - 1) / T, T>>>(ei, w);
    k_dis<<<(NNODES + T - 1) / T, T>>>();
    k_norm<<<(NEDGES + T - 1) / T, T>>>(w);

    // first props (F=128): x -> g_ax, h -> g_ah
    k_spmm_init<128, 0><<<(NNODES * 32 + T - 1) / T, T>>>(x);
    k_spmm_edges<128, 0><<<(NEDGES * 32 + T - 1) / T, T>>>(x);
    k_spmm_init<128, 1><<<(NNODES * 32 + T - 1) / T, T>>>(h);
    k_spmm_edges<128, 1><<<(NEDGES * 32 + T - 1) / T, T>>>(h);

    // layer-1 GEMM + relu (8 gate-streams), layer-2 GEMM (4 gates, x+h fused)
    dim3 g1((NNODES + 63) / 64, 8);
    k_gemm1<<<g1, 256>>>(Wx0, Wh0, bx0, bh0);
    dim3 g2((NNODES + 63) / 64, 4);
    k_gemm2<<<g2, 256>>>(Wx1, Wh1);

    // single fused second prop over all 4 gates (F=512): g_y -> g_G
    k_spmm_init<512, 2><<<(NNODES * 128 + T - 1) / T, T>>>(nullptr);
    k_spmm_edges<512, 2><<<(NEDGES * 128 + T - 1) / T, T>>>(nullptr);

    // LSTM elementwise
    k_lstm<<<(NNODES * HD + T - 1) / T, T>>>(c, bx1, bh1, wc, bg, out);
}

// round 4
// speedup vs baseline: 1.9421x; 1.9421x over previous
#include <cuda_runtime.h>
#include <math.h>

#define NNODES 20000
#define NEDGES 320000
#define HD 128

// ---------------- scratch (static device allocations) ----------------
__device__ int   g_is64;
__device__ __align__(16) float g_deg[NNODES];
__device__ __align__(16) int   g_cnt[NNODES];
__device__ __align__(16) int   g_rowptr[NNODES + 1];
__device__ __align__(16) int   g_cur[NNODES];
__device__ __align__(16) float g_dis[NNODES];
__device__ __align__(16) int   g_src[NEDGES];
__device__ __align__(16) int   g_dst[NEDGES];
__device__ __align__(16) int   g_ecol[NEDGES];    // CSR (by dst): src node
__device__ __align__(16) float g_enorm[NEDGES];   // CSR (by dst): edge norm
__device__ __align__(16) float g_ax[(size_t)NNODES * HD];   // prop(x)
__device__ __align__(16) float g_ah[(size_t)NNODES * HD];   // prop(h)
__device__ __align__(16) float g_z[(size_t)NNODES * 1024];  // relu layer-1: [N][x gates | h gates]
__device__ __align__(16) float g_y[(size_t)NNODES * 512];   // pre-prop gate features

// ---------------- dtype detection for edge_index (int32 vs int64) ----------------
__global__ void k_detect(const int* __restrict__ ei32) {
    __shared__ int nz;
    if (threadIdx.x == 0) nz = 0;
    __syncthreads();
    int v = ei32[2 * threadIdx.x + 1];
    if (v != 0) atomicAdd(&nz, 1);
    __syncthreads();
    if (threadIdx.x == 0) g_is64 = (nz == 0) ? 1 : 0;
}

// ---------------- init deg/cnt ----------------
__global__ void k_init() {
    int i = blockIdx.x * blockDim.x + threadIdx.x;
    if (i < NNODES) { g_deg[i] = 1.0f; g_cnt[i] = 0; }   // self-loop weight 1
}

// ---------------- edge decode + histograms ----------------
__global__ void k_edge_prep(const void* __restrict__ ei_raw,
                            const float* __restrict__ w) {
    int e = blockIdx.x * blockDim.x + threadIdx.x;
    if (e >= NEDGES) return;
    int s, d;
    if (g_is64) {
        const long long* ei = (const long long*)ei_raw;
        s = (int)ei[e];
        d = (int)ei[NEDGES + e];
    } else {
        const int* ei = (const int*)ei_raw;
        s = ei[e];
        d = ei[NEDGES + e];
    }
    if ((unsigned)s >= NNODES) s = 0;
    if ((unsigned)d >= NNODES) d = 0;
    g_src[e] = s;
    g_dst[e] = d;
    atomicAdd(&g_deg[d], w[e]);
    atomicAdd(&g_cnt[d], 1);
}

// ---------------- single-block scan (rowptr) + dis ----------------
__global__ void k_scan() {
    __shared__ int part[1024];
    const int t = threadIdx.x;
    const int SEG = (NNODES + 1023) / 1024;  // 20
    int base = t * SEG;
    int s = 0;
    for (int i = 0; i < SEG; i++) {
        int idx = base + i;
        if (idx < NNODES) s += g_cnt[idx];
    }
    part[t] = s;
    __syncthreads();
    for (int off = 1; off < 1024; off <<= 1) {
        int v = (t >= off) ? part[t - off] : 0;
        __syncthreads();
        part[t] += v;
        __syncthreads();
    }
    int run = (t == 0) ? 0 : part[t - 1];
    for (int i = 0; i < SEG; i++) {
        int idx = base + i;
        if (idx < NNODES) {
            g_rowptr[idx] = run;
            g_cur[idx] = run;
            run += g_cnt[idx];
        }
    }
    if (t == 1023) g_rowptr[NNODES] = NEDGES;
    // dis = deg^-1/2
    for (int i = t; i < NNODES; i += 1024) {
        float dg = g_deg[i];
        g_dis[i] = dg > 0.f ? rsqrtf(fmaxf(dg, 1e-12f)) : 0.f;
    }
}

// ---------------- scatter edges into CSR + compute norm ----------------
__global__ void k_scatter(const float* __restrict__ w) {
    int e = blockIdx.x * blockDim.x + threadIdx.x;
    if (e >= NEDGES) return;
    int s = g_src[e];
    int d = g_dst[e];
    int pos = atomicAdd(&g_cur[d], 1);
    g_ecol[pos] = s;
    g_enorm[pos] = g_dis[s] * w[e] * g_dis[d];
}

// ---------------- fused gather SpMM for x and h (F=128), one warp per node ----------------
__global__ void k_gather_xh(const float* __restrict__ x, const float* __restrict__ h) {
    int warp = (blockIdx.x * blockDim.x + threadIdx.x) >> 5;
    int lane = threadIdx.x & 31;
    if (warp >= NNODES) return;
    int n = warp;
    float sd = g_dis[n];
    float s2 = sd * sd;
    const float4* xq = (const float4*)(x + (size_t)n * HD) + lane;
    const float4* hq = (const float4*)(h + (size_t)n * HD) + lane;
    float4 xv = *xq, hv = *hq;
    float4 ax = make_float4(s2 * xv.x, s2 * xv.y, s2 * xv.z, s2 * xv.w);
    float4 ah = make_float4(s2 * hv.x, s2 * hv.y, s2 * hv.z, s2 * hv.w);
    int e0 = g_rowptr[n], e1 = g_rowptr[n + 1];
    for (int e = e0; e < e1; ++e) {
        int c = g_ecol[e];
        float nm = g_enorm[e];
        float4 cx = *((const float4*)(x + (size_t)c * HD) + lane);
        float4 ch = *((const float4*)(h + (size_t)c * HD) + lane);
        ax.x = fmaf(nm, cx.x, ax.x); ax.y = fmaf(nm, cx.y, ax.y);
        ax.z = fmaf(nm, cx.z, ax.z); ax.w = fmaf(nm, cx.w, ax.w);
        ah.x = fmaf(nm, ch.x, ah.x); ah.y = fmaf(nm, ch.y, ah.y);
        ah.z = fmaf(nm, ch.z, ah.z); ah.w = fmaf(nm, ch.w, ah.w);
    }
    ((float4*)(g_ax + (size_t)n * HD))[lane] = ax;
    ((float4*)(g_ah + (size_t)n * HD))[lane] = ah;
}

// ---------------- tiled SGEMM: C = act(sum_s A_s[M,128] @ B_s[128,128] + bias) ----------------
// BM=64, BN=128, BK=16, 256 threads, 4x8 microtile per thread.
template<int NS, bool RELU>
__device__ __forceinline__ void gemm_tile(
    const float* A0, const float* A1, int lda,
    const float* B0, const float* B1,
    const float* bias, float* C, int ldc)
{
    __shared__ float As[16][68];    // [k][row], padded
    __shared__ float Bs[16][128];   // [k][col]

    int tid = threadIdx.x;
    int tcx = tid & 15;     // 16 col groups of 8
    int trx = tid >> 4;     // 16 row groups of 4
    int row0 = blockIdx.x * 64;

    float acc[4][8];
#pragma unroll
    for (int m = 0; m < 4; m++)
#pragma unroll
        for (int n = 0; n < 8; n++) acc[m][n] = 0.f;

    int lq = tid & 3;       // which float4 along k in A row
    int lr = tid >> 2;      // A row 0..63
    int bi = tid >> 5;      // B row base 0..7
    int bc = tid & 31;      // B col quad

#pragma unroll
    for (int s = 0; s < NS; ++s) {
        const float* A = (s == 0) ? A0 : A1;
        const float* B = (s == 0) ? B0 : B1;
        for (int k0 = 0; k0 < 128; k0 += 16) {
            __syncthreads();
            float4 av = make_float4(0.f, 0.f, 0.f, 0.f);
            int grow = row0 + lr;
            if (grow < NNODES)
                av = *(const float4*)(A + (size_t)grow * lda + k0 + 4 * lq);
            As[4 * lq + 0][lr] = av.x;
            As[4 * lq + 1][lr] = av.y;
            As[4 * lq + 2][lr] = av.z;
            As[4 * lq + 3][lr] = av.w;
            *(float4*)&Bs[bi][bc * 4]     = *(const float4*)(B + (k0 + bi) * 128 + bc * 4);
            *(float4*)&Bs[bi + 8][bc * 4] = *(const float4*)(B + (k0 + bi + 8) * 128 + bc * 4);
            __syncthreads();
#pragma unroll
            for (int k = 0; k < 16; k++) {
                float a[4];
#pragma unroll
                for (int m = 0; m < 4; m++) a[m] = As[k][trx * 4 + m];
                float4 b0 = *(float4*)&Bs[k][tcx * 8];
                float4 b1 = *(float4*)&Bs[k][tcx * 8 + 4];
                float bb[8] = {b0.x, b0.y, b0.z, b0.w, b1.x, b1.y, b1.z, b1.w};
#pragma unroll
                for (int m = 0; m < 4; m++)
#pragma unroll
                    for (int n = 0; n < 8; n++)
                        acc[m][n] = fmaf(a[m], bb[n], acc[m][n]);
            }
        }
    }
#pragma unroll
    for (int m = 0; m < 4; m++) {
        int grow = row0 + trx * 4 + m;
        if (grow >= NNODES) continue;
#pragma unroll
        for (int n = 0; n < 8; n++) {
            int col = tcx * 8 + n;
            float v = acc[m][n];
            if (bias) v += bias[col];
            if (RELU) v = fmaxf(v, 0.f);
            C[(size_t)grow * ldc + col] = v;
        }
    }
}

// layer 1: z[:, sg*128 .. +128] = relu(a_s @ W0_s[g] + b0_s[g]),  sg = s*4+g
__global__ void k_gemm1(const float* __restrict__ Wx0, const float* __restrict__ Wh0,
                        const float* __restrict__ bx0, const float* __restrict__ bh0) {
    int sg = blockIdx.y;
    int s = sg >> 2, g = sg & 3;
    const float* A    = s ? g_ah : g_ax;
    const float* W    = (s ? Wh0 : Wx0) + g * 128 * 128;
    const float* bias = (s ? bh0 : bx0) + g * 128;
    gemm_tile<1, true>(A, nullptr, 128, W, nullptr, bias, g_z + sg * 128, 1024);
}

// layer 2 (pre-prop, NO bias): y[:, g*128..] = z_x[g] @ Wx1[g] + z_h[g] @ Wh1[g]
__global__ void k_gemm2(const float* __restrict__ Wx1, const float* __restrict__ Wh1) {
    int g = blockIdx.y;
    gemm_tile<2, false>(g_z + g * 128, g_z + 512 + g * 128, 1024,
                        Wx1 + g * 128 * 128, Wh1 + g * 128 * 128,
                        nullptr, g_y + g * 128, 512);
}

// ---------------- fused F=512 gather + LSTM epilogue: one block (128 thr) per node ----------------
__device__ __forceinline__ float sigmoidf_(float v) { return 1.f / (1.f + expf(-v)); }

__global__ void __launch_bounds__(128) k_gather_lstm(
    const float* __restrict__ c,
    const float* __restrict__ bx1, const float* __restrict__ bh1,
    const float* __restrict__ wc, const float* __restrict__ bg,
    float* __restrict__ out)
{
    __shared__ float sG[512];
    int n = blockIdx.x;
    int t = threadIdx.x;
    float sd = g_dis[n];
    float s2 = sd * sd;
    float4 v = ((const float4*)(g_y + (size_t)n * 512))[t];
    float4 acc = make_float4(s2 * v.x, s2 * v.y, s2 * v.z, s2 * v.w);
    int e0 = g_rowptr[n], e1 = g_rowptr[n + 1];
    for (int e = e0; e < e1; ++e) {
        int cc = g_ecol[e];
        float nm = g_enorm[e];
        float4 yv = ((const float4*)(g_y + (size_t)cc * 512))[t];
        acc.x = fmaf(nm, yv.x, acc.x); acc.y = fmaf(nm, yv.y, acc.y);
        acc.z = fmaf(nm, yv.z, acc.z); acc.w = fmaf(nm, yv.w, acc.w);
    }
    ((float4*)sG)[t] = acc;
    __syncthreads();
    // LSTM: thread t handles feature f = t (128 features)
    int f = t;
    int idx = n * HD + f;
    float cv = c[idx];
    float Gi = sG[f]       + bx1[f]       + bh1[f];
    float Gf = sG[128 + f] + bx1[128 + f] + bh1[128 + f];
    float Gc = sG[256 + f] + bx1[256 + f] + bh1[256 + f];
    float Go = sG[384 + f] + bx1[384 + f] + bh1[384 + f];
    float I  = sigmoidf_(Gi + wc[f] * cv + bg[f]);
    float Fg = sigmoidf_(Gf + wc[128 + f] * cv + bg[128 + f]);
    float T  = tanhf(Gc + bg[256 + f]);
    float Cn = Fg * cv + I * T;
    float O  = sigmoidf_(Go + wc[256 + f] * Cn + bg[384 + f]);
    float Hn = O * tanhf(Cn);
    out[idx] = Hn;
    out[(size_t)NNODES * HD + idx] = Cn;
}

// ---------------- launch ----------------
extern "C" void kernel_launch(void* const* d_in, const int* in_sizes, int n_in,
                              void* d_out, int out_size) {
    const float* x   = (const float*)d_in[0];
    const void*  ei  = d_in[1];                 // int32 or int64, detected on device
    const float* w   = (const float*)d_in[2];
    const float* h   = (const float*)d_in[3];
    const float* c   = (const float*)d_in[4];
    const float* Wx0 = (const float*)d_in[5];
    const float* bx0 = (const float*)d_in[6];
    const float* Wx1 = (const float*)d_in[7];
    const float* bx1 = (const float*)d_in[8];
    const float* Wh0 = (const float*)d_in[9];
    const float* bh0 = (const float*)d_in[10];
    const float* Wh1 = (const float*)d_in[11];
    const float* bh1 = (const float*)d_in[12];
    const float* wc  = (const float*)d_in[13];
    const float* bg  = (const float*)d_in[14];
    float* out = (float*)d_out;

    const int T = 256;
    // 1-5: prologue (detect, init, edge prep, scan+dis, CSR scatter+norm)
    k_detect<<<1, 128>>>((const int*)ei);
    k_init<<<(NNODES + T - 1) / T, T>>>();
    k_edge_prep<<<(NEDGES + T - 1) / T, T>>>(ei, w);
    k_scan<<<1, 1024>>>();
    k_scatter<<<(NEDGES + T - 1) / T, T>>>(w);

    // 6: fused first props (F=128) for x and h, gather-based
    k_gather_xh<<<(NNODES * 32 + T - 1) / T, T>>>(x, h);

    // 7-8: GEMMs
    dim3 g1((NNODES + 63) / 64, 8);
    k_gemm1<<<g1, 256>>>(Wx0, Wh0, bx0, bh0);
    dim3 g2((NNODES + 63) / 64, 4);
    k_gemm2<<<g2, 256>>>(Wx1, Wh1);

    // 9: fused F=512 gather + LSTM epilogue
    k_gather_lstm<<<NNODES, 128>>>(c, bx1, bh1, wc, bg, out);
}

// round 5
// speedup vs baseline: 2.1072x; 1.0850x over previous
#include <cuda_runtime.h>
#include <math.h>

#define NNODES 20000
#define NEDGES 320000
#define HD 128
#define APAD 68

// ---------------- scratch (static device allocations) ----------------
__device__ int   g_is64;
__device__ __align__(16) float g_deg[NNODES];
__device__ __align__(16) int   g_cnt[NNODES];
__device__ __align__(16) int   g_rowptr[NNODES + 4];
__device__ __align__(16) int   g_cur[NNODES + 4];
__device__ __align__(16) float g_dis[NNODES];
__device__ __align__(16) int   g_src[NEDGES];
__device__ __align__(16) int   g_dst[NEDGES];
__device__ __align__(16) int   g_ecol[NEDGES];    // CSR (by dst): src node
__device__ __align__(16) float g_enorm[NEDGES];   // CSR (by dst): edge norm
__device__ __align__(16) float g_ax[(size_t)NNODES * HD];   // prop(x)
__device__ __align__(16) float g_ah[(size_t)NNODES * HD];   // prop(h)
__device__ __align__(16) float g_z[(size_t)NNODES * 1024];  // relu layer-1: [N][x gates | h gates]
__device__ __align__(16) float g_y[(size_t)NNODES * 512];   // pre-prop gate features
// pre-split / pre-swizzled weights: [stream 16][ks 16][nt 16][lane 32] = (b0hi,b1hi,b0lo,b1lo)
__device__ __align__(16) uint4 g_Bp[16 * 16 * 16 * 32];

__device__ __forceinline__ unsigned tf32_rna(float f) {
    unsigned u; asm("cvt.rna.tf32.f32 %0, %1;" : "=r"(u) : "f"(f)); return u;
}

// ---------------- dtype detection for edge_index (int32 vs int64) ----------------
__global__ void k_detect(const int* __restrict__ ei32) {
    __shared__ int nz;
    if (threadIdx.x == 0) nz = 0;
    __syncthreads();
    int v = ei32[2 * threadIdx.x + 1];
    if (v != 0) atomicAdd(&nz, 1);
    __syncthreads();
    if (threadIdx.x == 0) g_is64 = (nz == 0) ? 1 : 0;
}

// ---------------- init deg/cnt ----------------
__global__ void k_init() {
    int i = blockIdx.x * blockDim.x + threadIdx.x;
    if (i < NNODES) { g_deg[i] = 1.0f; g_cnt[i] = 0; }   // self-loop weight 1
}

// ---------------- edge decode + histograms ----------------
__global__ void k_edge_prep(const void* __restrict__ ei_raw,
                            const float* __restrict__ w) {
    int e = blockIdx.x * blockDim.x + threadIdx.x;
    if (e >= NEDGES) return;
    int s, d;
    if (g_is64) {
        const long long* ei = (const long long*)ei_raw;
        s = (int)ei[e];
        d = (int)ei[NEDGES + e];
    } else {
        const int* ei = (const int*)ei_raw;
        s = ei[e];
        d = ei[NEDGES + e];
    }
    if ((unsigned)s >= NNODES) s = 0;
    if ((unsigned)d >= NNODES) d = 0;
    g_src[e] = s;
    g_dst[e] = d;
    atomicAdd(&g_deg[d], w[e]);
    atomicAdd(&g_cnt[d], 1);
}

// ---------------- fast scan (rowptr) + dis: int4 loads + shuffle scan ----------------
__global__ void k_scan() {
    const int t = threadIdx.x;          // 1024 threads
    const int SEG = 20;
    int base = t * SEG;
    int v[SEG];
    int s = 0;
    if (base + SEG <= NNODES) {
#pragma unroll
        for (int i = 0; i < 5; i++) {
            int4 q = *(const int4*)(g_cnt + base + i * 4);
            v[i * 4 + 0] = q.x; v[i * 4 + 1] = q.y; v[i * 4 + 2] = q.z; v[i * 4 + 3] = q.w;
            s += q.x + q.y + q.z + q.w;
        }
    } else {
#pragma unroll
        for (int i = 0; i < SEG; i++) { v[i] = 0; }
    }
    int lane = t & 31, wid = t >> 5;
    int incl = s;
#pragma unroll
    for (int off = 1; off < 32; off <<= 1) {
        int n = __shfl_up_sync(0xFFFFFFFFu, incl, off);
        if (lane >= off) incl += n;
    }
    __shared__ int wsum[32];
    if (lane == 31) wsum[wid] = incl;
    __syncthreads();
    if (wid == 0) {
        int wv = wsum[lane];
        int wi = wv;
#pragma unroll
        for (int off = 1; off < 32; off <<= 1) {
            int n = __shfl_up_sync(0xFFFFFFFFu, wi, off);
            if (lane >= off) wi += n;
        }
        wsum[lane] = wi - wv;   // exclusive
    }
    __syncthreads();
    int run = wsum[wid] + incl - s;   // exclusive base for this thread
    if (base + SEG <= NNODES) {
        int rp[SEG];
#pragma unroll
        for (int i = 0; i < SEG; i++) { rp[i] = run; run += v[i]; }
#pragma unroll
        for (int i = 0; i < 5; i++) {
            int4 q = make_int4(rp[i * 4], rp[i * 4 + 1], rp[i * 4 + 2], rp[i * 4 + 3]);
            *(int4*)(g_rowptr + base + i * 4) = q;
            *(int4*)(g_cur + base + i * 4) = q;
        }
    }
    if (t == 1023) g_rowptr[NNODES] = NEDGES;
    // dis = deg^-1/2
    for (int i = t; i < NNODES; i += 1024) {
        float dg = g_deg[i];
        g_dis[i] = dg > 0.f ? rsqrtf(fmaxf(dg, 1e-12f)) : 0.f;
    }
}

// ---------------- scatter edges into CSR + compute norm ----------------
__global__ void k_scatter(const float* __restrict__ w) {
    int e = blockIdx.x * blockDim.x + threadIdx.x;
    if (e >= NEDGES) return;
    int s = g_src[e];
    int d = g_dst[e];
    int pos = atomicAdd(&g_cur[d], 1);
    g_ecol[pos] = s;
    g_enorm[pos] = g_dis[s] * w[e] * g_dis[d];
}

// ---------------- weight prep: split hi/lo tf32 + swizzle to B-fragment order ----------------
// streams: 0-3 Wx0[g], 4-7 Wh0[g], 8-11 Wx1[g], 12-15 Wh1[g]
__global__ void k_wprep(const float* __restrict__ Wx0, const float* __restrict__ Wh0,
                        const float* __restrict__ Wx1, const float* __restrict__ Wh1) {
    int idx = blockIdx.x * blockDim.x + threadIdx.x;    // 16*16*16*32 = 131072
    if (idx >= 16 * 16 * 16 * 32) return;
    int s    = idx >> 13;          // stream
    int rem  = idx & 8191;
    int ks   = rem >> 9;           // k-step (k0 = ks*8)
    int rem2 = rem & 511;
    int nt   = rem2 >> 5;          // n-tile (n0 = nt*8)
    int lane = rem2 & 31;
    const float* W;
    if (s < 4)       W = Wx0 + s * 16384;
    else if (s < 8)  W = Wh0 + (s - 4) * 16384;
    else if (s < 12) W = Wx1 + (s - 8) * 16384;
    else             W = Wh1 + (s - 12) * 16384;
    int tig = lane & 3, grp = lane >> 2;
    int k0 = ks * 8, n = nt * 8 + grp;
    float w0 = W[(k0 + tig) * 128 + n];
    float w1 = W[(k0 + tig + 4) * 128 + n];
    unsigned h0 = tf32_rna(w0), h1 = tf32_rna(w1);
    unsigned l0 = tf32_rna(w0 - __uint_as_float(h0));
    unsigned l1 = tf32_rna(w1 - __uint_as_float(h1));
    g_Bp[idx] = make_uint4(h0, h1, l0, l1);
}

// ---------------- fused gather SpMM for x and h (F=128), one warp per node ----------------
__global__ void k_gather_xh(const float* __restrict__ x, const float* __restrict__ h) {
    int warp = (blockIdx.x * blockDim.x + threadIdx.x) >> 5;
    int lane = threadIdx.x & 31;
    if (warp >= NNODES) return;
    int n = warp;
    float sd = g_dis[n];
    float s2 = sd * sd;
    float4 xv = *((const float4*)(x + (size_t)n * HD) + lane);
    float4 hv = *((const float4*)(h + (size_t)n * HD) + lane);
    float4 ax = make_float4(s2 * xv.x, s2 * xv.y, s2 * xv.z, s2 * xv.w);
    float4 ah = make_float4(s2 * hv.x, s2 * hv.y, s2 * hv.z, s2 * hv.w);
    int e0 = g_rowptr[n], e1 = g_rowptr[n + 1];
    for (int e = e0; e < e1; ++e) {
        int c = g_ecol[e];
        float nm = g_enorm[e];
        float4 cx = *((const float4*)(x + (size_t)c * HD) + lane);
        float4 ch = *((const float4*)(h + (size_t)c * HD) + lane);
        ax.x = fmaf(nm, cx.x, ax.x); ax.y = fmaf(nm, cx.y, ax.y);
        ax.z = fmaf(nm, cx.z, ax.z); ax.w = fmaf(nm, cx.w, ax.w);
        ah.x = fmaf(nm, ch.x, ah.x); ah.y = fmaf(nm, ch.y, ah.y);
        ah.z = fmaf(nm, ch.z, ah.z); ah.w = fmaf(nm, ch.w, ah.w);
    }
    ((float4*)(g_ax + (size_t)n * HD))[lane] = ax;
    ((float4*)(g_ah + (size_t)n * HD))[lane] = ah;
}

// ---------------- tensor-core GEMM core (m16n8k8 tf32, 3-term split) ----------------
// block: 256 threads = 8 warps (2 m x 4 n), tile 128x128, K streamed in 2 chunks of 64.
#define MMA_TF32(c, a, bb0, bb1) \
    asm("mma.sync.aligned.m16n8k8.row.col.f32.tf32.tf32.f32 " \
        "{%0,%1,%2,%3},{%4,%5,%6,%7},{%8,%9},{%0,%1,%2,%3};" \
        : "+f"(c[0]), "+f"(c[1]), "+f"(c[2]), "+f"(c[3]) \
        : "r"(a[0]), "r"(a[1]), "r"(a[2]), "r"(a[3]), "r"(bb0), "r"(bb1))

__device__ __forceinline__ void gemm_source(float (*acc)[4][4],
                                            const float* __restrict__ A, int lda,
                                            int stream, int row0, float* As) {
    int tid = threadIdx.x;
    int wid = tid >> 5, lane = tid & 31;
    int wm = wid >> 2, wn = wid & 3;
    int m0 = wm * 64, tig = lane & 3, grp = lane >> 2;
    const uint4* __restrict__ Bp = g_Bp + (stream << 13);

    for (int chunk = 0; chunk < 2; chunk++) {
        __syncthreads();
#pragma unroll
        for (int i = 0; i < 8; i++) {
            int f = i * 256 + tid;            // 0..2047
            int row = f >> 4, c4 = (f & 15) * 4;
            float4 v = make_float4(0.f, 0.f, 0.f, 0.f);
            int grow = row0 + row;
            if (grow < NNODES)
                v = *(const float4*)(A + (size_t)grow * lda + chunk * 64 + c4);
            *(float4*)&As[row * APAD + c4] = v;
        }
        __syncthreads();
#pragma unroll 2
        for (int ksl = 0; ksl < 8; ksl++) {
            int ks = chunk * 8 + ksl;
            unsigned ahi[4][4], alo[4][4];
#pragma unroll
            for (int mt = 0; mt < 4; mt++) {
                int rb = (m0 + mt * 16 + grp) * APAD;
                int kc = ksl * 8 + tig;
                float a0 = As[rb + kc];
                float a1 = As[rb + 8 * APAD + kc];
                float a2 = As[rb + kc + 4];
                float a3 = As[rb + 8 * APAD + kc + 4];
                ahi[mt][0] = tf32_rna(a0); alo[mt][0] = tf32_rna(a0 - __uint_as_float(ahi[mt][0]));
                ahi[mt][1] = tf32_rna(a1); alo[mt][1] = tf32_rna(a1 - __uint_as_float(ahi[mt][1]));
                ahi[mt][2] = tf32_rna(a2); alo[mt][2] = tf32_rna(a2 - __uint_as_float(ahi[mt][2]));
                ahi[mt][3] = tf32_rna(a3); alo[mt][3] = tf32_rna(a3 - __uint_as_float(ahi[mt][3]));
            }
#pragma unroll
            for (int nt = 0; nt < 4; nt++) {
                uint4 b = Bp[(ks * 16 + wn * 4 + nt) * 32 + lane];
#pragma unroll
                for (int mt = 0; mt < 4; mt++) {
                    float* c = acc[mt][nt];
                    MMA_TF32(c, ahi[mt], b.x, b.y);   // hi*hi
                    MMA_TF32(c, ahi[mt], b.z, b.w);   // hi*lo
                    MMA_TF32(c, alo[mt], b.x, b.y);   // lo*hi
                }
            }
        }
    }
}

template<bool BIASRELU>
__device__ __forceinline__ void gemm_epilogue(float (*acc)[4][4],
                                              const float* __restrict__ bias,
                                              float* __restrict__ C, int ldc, int row0) {
    int tid = threadIdx.x;
    int wid = tid >> 5, lane = tid & 31;
    int wm = wid >> 2, wn = wid & 3;
    int m0 = wm * 64, n0 = wn * 32;
    int tig = lane & 3, grp = lane >> 2;
#pragma unroll
    for (int nt = 0; nt < 4; nt++) {
        int col = n0 + nt * 8 + 2 * tig;
        float b0 = BIASRELU ? bias[col] : 0.f;
        float b1 = BIASRELU ? bias[col + 1] : 0.f;
#pragma unroll
        for (int mt = 0; mt < 4; mt++) {
            int r = row0 + m0 + mt * 16 + grp;
            float* c = acc[mt][nt];
            if (r < NNODES) {
                float u0 = c[0] + b0, u1 = c[1] + b1;
                if (BIASRELU) { u0 = fmaxf(u0, 0.f); u1 = fmaxf(u1, 0.f); }
                *(float2*)&C[(size_t)r * ldc + col] = make_float2(u0, u1);
            }
            int r2 = r + 8;
            if (r2 < NNODES) {
                float u2 = c[2] + b0, u3 = c[3] + b1;
                if (BIASRELU) { u2 = fmaxf(u2, 0.f); u3 = fmaxf(u3, 0.f); }
                *(float2*)&C[(size_t)r2 * ldc + col] = make_float2(u2, u3);
            }
        }
    }
}

// layer 1: z[:, sg*128..] = relu(a_s @ W0[g] + b0[g]), sg = s*4+g
__global__ __launch_bounds__(256) void k_mma1(const float* __restrict__ bx0,
                                              const float* __restrict__ bh0) {
    __shared__ float As[128 * APAD];
    int sg = blockIdx.y;
    int row0 = blockIdx.x * 128;
    float acc[4][4][4];
#pragma unroll
    for (int a = 0; a < 4; a++)
#pragma unroll
        for (int b = 0; b < 4; b++)
#pragma unroll
            for (int cc = 0; cc < 4; cc++) acc[a][b][cc] = 0.f;
    const float* A = (sg < 4) ? g_ax : g_ah;
    gemm_source(acc, A, 128, sg, row0, As);
    const float* bias = ((sg < 4) ? bx0 : bh0) + (sg & 3) * 128;
    gemm_epilogue<true>(acc, bias, g_z + sg * 128, 1024, row0);
}

// layer 2 (pre-prop, NO bias): y[:, g*128..] = z_x[g] @ Wx1[g] + z_h[g] @ Wh1[g]
__global__ __launch_bounds__(256) void k_mma2() {
    __shared__ float As[128 * APAD];
    int g = blockIdx.y;
    int row0 = blockIdx.x * 128;
    float acc[4][4][4];
#pragma unroll
    for (int a = 0; a < 4; a++)
#pragma unroll
        for (int b = 0; b < 4; b++)
#pragma unroll
            for (int cc = 0; cc < 4; cc++) acc[a][b][cc] = 0.f;
    gemm_source(acc, g_z + g * 128, 1024, 8 + g, row0, As);
    gemm_source(acc, g_z + 512 + g * 128, 1024, 12 + g, row0, As);
    gemm_epilogue<false>(acc, nullptr, g_y + g * 128, 512, row0);
}

// ---------------- fused F=512 gather + LSTM epilogue: one block (128 thr) per node ----------------
__device__ __forceinline__ float sigmoidf_(float v) { return 1.f / (1.f + expf(-v)); }

__global__ void __launch_bounds__(128) k_gather_lstm(
    const float* __restrict__ c,
    const float* __restrict__ bx1, const float* __restrict__ bh1,
    const float* __restrict__ wc, const float* __restrict__ bg,
    float* __restrict__ out)
{
    __shared__ float sG[512];
    int n = blockIdx.x;
    int t = threadIdx.x;
    float sd = g_dis[n];
    float s2 = sd * sd;
    float4 v = ((const float4*)(g_y + (size_t)n * 512))[t];
    float4 acc = make_float4(s2 * v.x, s2 * v.y, s2 * v.z, s2 * v.w);
    int e0 = g_rowptr[n], e1 = g_rowptr[n + 1];
    for (int e = e0; e < e1; ++e) {
        int cc = g_ecol[e];
        float nm = g_enorm[e];
        float4 yv = ((const float4*)(g_y + (size_t)cc * 512))[t];
        acc.x = fmaf(nm, yv.x, acc.x); acc.y = fmaf(nm, yv.y, acc.y);
        acc.z = fmaf(nm, yv.z, acc.z); acc.w = fmaf(nm, yv.w, acc.w);
    }
    ((float4*)sG)[t] = acc;
    __syncthreads();
    int f = t;
    int idx = n * HD + f;
    float cv = c[idx];
    float Gi = sG[f]       + bx1[f]       + bh1[f];
    float Gf = sG[128 + f] + bx1[128 + f] + bh1[128 + f];
    float Gc = sG[256 + f] + bx1[256 + f] + bh1[256 + f];
    float Go = sG[384 + f] + bx1[384 + f] + bh1[384 + f];
    float I  = sigmoidf_(Gi + wc[f] * cv + bg[f]);
    float Fg = sigmoidf_(Gf + wc[128 + f] * cv + bg[128 + f]);
    float T  = tanhf(Gc + bg[256 + f]);
    float Cn = Fg * cv + I * T;
    float O  = sigmoidf_(Go + wc[256 + f] * Cn + bg[384 + f]);
    float Hn = O * tanhf(Cn);
    out[idx] = Hn;
    out[(size_t)NNODES * HD + idx] = Cn;
}

// ---------------- launch ----------------
extern "C" void kernel_launch(void* const* d_in, const int* in_sizes, int n_in,
                              void* d_out, int out_size) {
    const float* x   = (const float*)d_in[0];
    const void*  ei  = d_in[1];                 // int32 or int64, detected on device
    const float* w   = (const float*)d_in[2];
    const float* h   = (const float*)d_in[3];
    const float* c   = (const float*)d_in[4];
    const float* Wx0 = (const float*)d_in[5];
    const float* bx0 = (const float*)d_in[6];
    const float* Wx1 = (const float*)d_in[7];
    const float* bx1 = (const float*)d_in[8];
    const float* Wh0 = (const float*)d_in[9];
    const float* bh0 = (const float*)d_in[10];
    const float* Wh1 = (const float*)d_in[11];
    const float* bh1 = (const float*)d_in[12];
    const float* wc  = (const float*)d_in[13];
    const float* bg  = (const float*)d_in[14];
    float* out = (float*)d_out;

    const int T = 256;
    // prologue: detect, init, weight prep, edge prep, scan+dis, CSR scatter+norm
    k_detect<<<1, 128>>>((const int*)ei);
    k_init<<<(NNODES + T - 1) / T, T>>>();
    k_wprep<<<(16 * 16 * 16 * 32 + T - 1) / T, T>>>(Wx0, Wh0, Wx1, Wh1);
    k_edge_prep<<<(NEDGES + T - 1) / T, T>>>(ei, w);
    k_scan<<<1, 1024>>>();
    k_scatter<<<(NEDGES + T - 1) / T, T>>>(w);

    // fused first props (F=128) for x and h, gather-based
    k_gather_xh<<<(NNODES * 32 + T - 1) / T, T>>>(x, h);

    // tensor-core GEMMs
    dim3 g1((NNODES + 127) / 128, 8);
    k_mma1<<<g1, 256>>>(bx0, bh0);
    dim3 g2((NNODES + 127) / 128, 4);
    k_mma2<<<g2, 256>>>();

    // fused F=512 gather + LSTM epilogue
    k_gather_lstm<<<NNODES, 128>>>(c, bx1, bh1, wc, bg, out);
}

// round 6
// speedup vs baseline: 4.0595x; 1.9265x over previous
#include <cuda_runtime.h>
#include <math.h>

#define NNODES 20000
#define NEDGES 320000
#define HD 128
#define ASTRIDE 36

// ---------------- scratch (static device allocations) ----------------
__device__ int   g_is64;
__device__ __align__(16) float g_deg[NNODES];
__device__ __align__(16) int   g_cnt[NNODES];
__device__ __align__(16) int   g_rowptr[NNODES + 4];
__device__ __align__(16) int   g_cur[NNODES + 4];
__device__ __align__(16) float g_dis[NNODES];
__device__ __align__(16) int   g_src[NEDGES];
__device__ __align__(16) int   g_dst[NEDGES];
__device__ __align__(16) int   g_ecol[NEDGES];    // CSR (by dst): src node
__device__ __align__(16) float g_enorm[NEDGES];   // CSR (by dst): edge norm
__device__ __align__(16) float g_ax[(size_t)NNODES * HD];   // prop(x)
__device__ __align__(16) float g_ah[(size_t)NNODES * HD];   // prop(h)
__device__ __align__(16) float g_z[(size_t)NNODES * 1024];  // relu layer-1: [N][x gates | h gates]
__device__ __align__(16) float g_y[(size_t)NNODES * 512];   // pre-prop gate features
// pre-split bf16 weights: [stream 16][ks 8][nt 16][lane 32] = (hi0,hi1,lo0,lo1)
__device__ __align__(16) uint4 g_Bp[16 * 8 * 16 * 32];

// bf16 truncation split of a k-pair (x0=even k, x1=odd k) into packed bf16x2 regs.
__device__ __forceinline__ void bf16_split_pair(float x0, float x1,
                                                unsigned &hi, unsigned &lo) {
    unsigned b0 = __float_as_uint(x0), b1 = __float_as_uint(x1);
    hi = __byte_perm(b0, b1, 0x7632);              // {lo16=top16(x0), hi16=top16(x1)}
    float l0 = x0 - __uint_as_float(b0 & 0xFFFF0000u);
    float l1 = x1 - __uint_as_float(b1 & 0xFFFF0000u);
    asm("cvt.rn.bf16x2.f32 %0, %1, %2;" : "=r"(lo) : "f"(l1), "f"(l0));
}

// ---------------- init deg/cnt + edge dtype detect (block 0) ----------------
__global__ void k_init(const int* __restrict__ ei32) {
    int i = blockIdx.x * blockDim.x + threadIdx.x;
    if (i < NNODES) { g_deg[i] = 1.0f; g_cnt[i] = 0; }   // self-loop weight 1
    if (blockIdx.x == 0) {
        __shared__ int nz;
        if (threadIdx.x == 0) nz = 0;
        __syncthreads();
        if (threadIdx.x < 128) {
            if (ei32[2 * threadIdx.x + 1] != 0) atomicAdd(&nz, 1);
        }
        __syncthreads();
        if (threadIdx.x == 0) g_is64 = (nz == 0) ? 1 : 0;
    }
}

// ---------------- edge decode + histograms ----------------
__global__ void k_edge_prep(const void* __restrict__ ei_raw,
                            const float* __restrict__ w) {
    int e = blockIdx.x * blockDim.x + threadIdx.x;
    if (e >= NEDGES) return;
    int s, d;
    if (g_is64) {
        const long long* ei = (const long long*)ei_raw;
        s = (int)ei[e];
        d = (int)ei[NEDGES + e];
    } else {
        const int* ei = (const int*)ei_raw;
        s = ei[e];
        d = ei[NEDGES + e];
    }
    if ((unsigned)s >= NNODES) s = 0;
    if ((unsigned)d >= NNODES) d = 0;
    g_src[e] = s;
    g_dst[e] = d;
    atomicAdd(&g_deg[d], w[e]);
    atomicAdd(&g_cnt[d], 1);
}

// ---------------- fast scan (rowptr) + dis ----------------
__global__ void k_scan() {
    const int t = threadIdx.x;          // 1024 threads
    const int SEG = 20;
    int base = t * SEG;
    int v[SEG];
    int s = 0;
    if (base + SEG <= NNODES) {
#pragma unroll
        for (int i = 0; i < 5; i++) {
            int4 q = *(const int4*)(g_cnt + base + i * 4);
            v[i * 4 + 0] = q.x; v[i * 4 + 1] = q.y; v[i * 4 + 2] = q.z; v[i * 4 + 3] = q.w;
            s += q.x + q.y + q.z + q.w;
        }
    } else {
#pragma unroll
        for (int i = 0; i < SEG; i++) { v[i] = 0; }
    }
    int lane = t & 31, wid = t >> 5;
    int incl = s;
#pragma unroll
    for (int off = 1; off < 32; off <<= 1) {
        int n = __shfl_up_sync(0xFFFFFFFFu, incl, off);
        if (lane >= off) incl += n;
    }
    __shared__ int wsum[32];
    if (lane == 31) wsum[wid] = incl;
    __syncthreads();
    if (wid == 0) {
        int wv = wsum[lane];
        int wi = wv;
#pragma unroll
        for (int off = 1; off < 32; off <<= 1) {
            int n = __shfl_up_sync(0xFFFFFFFFu, wi, off);
            if (lane >= off) wi += n;
        }
        wsum[lane] = wi - wv;   // exclusive
    }
    __syncthreads();
    int run = wsum[wid] + incl - s;   // exclusive base for this thread
    if (base + SEG <= NNODES) {
        int rp[SEG];
#pragma unroll
        for (int i = 0; i < SEG; i++) { rp[i] = run; run += v[i]; }
#pragma unroll
        for (int i = 0; i < 5; i++) {
            int4 q = make_int4(rp[i * 4], rp[i * 4 + 1], rp[i * 4 + 2], rp[i * 4 + 3]);
            *(int4*)(g_rowptr + base + i * 4) = q;
            *(int4*)(g_cur + base + i * 4) = q;
        }
    }
    if (t == 1023) g_rowptr[NNODES] = NEDGES;
    for (int i = t; i < NNODES; i += 1024) {
        float dg = g_deg[i];
        g_dis[i] = dg > 0.f ? rsqrtf(fmaxf(dg, 1e-12f)) : 0.f;
    }
}

// ---------------- scatter edges into CSR + compute norm ----------------
__global__ void k_scatter(const float* __restrict__ w) {
    int e = blockIdx.x * blockDim.x + threadIdx.x;
    if (e >= NEDGES) return;
    int s = g_src[e];
    int d = g_dst[e];
    int pos = atomicAdd(&g_cur[d], 1);
    g_ecol[pos] = s;
    g_enorm[pos] = g_dis[s] * w[e] * g_dis[d];
}

// ---------------- weight prep: bf16 hi/lo split, B-fragment order (m16n8k16) ----------------
// streams: 0-3 Wx0[g], 4-7 Wh0[g], 8-11 Wx1[g], 12-15 Wh1[g]
__global__ void k_wprep(const float* __restrict__ Wx0, const float* __restrict__ Wh0,
                        const float* __restrict__ Wx1, const float* __restrict__ Wh1) {
    int idx = blockIdx.x * blockDim.x + threadIdx.x;    // 16*8*16*32 = 65536
    if (idx >= 16 * 8 * 16 * 32) return;
    int s    = idx >> 12;          // stream
    int ks   = (idx >> 9) & 7;     // k-step (k0 = ks*16)
    int nt   = (idx >> 5) & 15;    // n-tile (n0 = nt*8)
    int lane = idx & 31;
    const float* W;
    if (s < 4)       W = Wx0 + s * 16384;
    else if (s < 8)  W = Wh0 + (s - 4) * 16384;
    else if (s < 12) W = Wx1 + (s - 8) * 16384;
    else             W = Wh1 + (s - 12) * 16384;
    int tig = lane & 3, grp = lane >> 2;
    int k0 = ks * 16, n = nt * 8 + grp;
    float w0 = W[(k0 + 2 * tig)     * 128 + n];
    float w1 = W[(k0 + 2 * tig + 1) * 128 + n];
    float w2 = W[(k0 + 2 * tig + 8) * 128 + n];
    float w3 = W[(k0 + 2 * tig + 9) * 128 + n];
    unsigned h0, l0, h1, l1;
    bf16_split_pair(w0, w1, h0, l0);
    bf16_split_pair(w2, w3, h1, l1);
    g_Bp[idx] = make_uint4(h0, h1, l0, l1);
}

// ---------------- fused gather SpMM for x and h (F=128), one warp per node ----------------
__global__ void k_gather_xh(const float* __restrict__ x, const float* __restrict__ h) {
    int warp = (blockIdx.x * blockDim.x + threadIdx.x) >> 5;
    int lane = threadIdx.x & 31;
    if (warp >= NNODES) return;
    int n = warp;
    float sd = g_dis[n];
    float s2 = sd * sd;
    float4 xv = *((const float4*)(x + (size_t)n * HD) + lane);
    float4 hv = *((const float4*)(h + (size_t)n * HD) + lane);
    float4 ax = make_float4(s2 * xv.x, s2 * xv.y, s2 * xv.z, s2 * xv.w);
    float4 ah = make_float4(s2 * hv.x, s2 * hv.y, s2 * hv.z, s2 * hv.w);
    int e0 = g_rowptr[n], e1 = g_rowptr[n + 1];
    for (int e = e0; e < e1; ++e) {
        int c = g_ecol[e];
        float nm = g_enorm[e];
        float4 cx = *((const float4*)(x + (size_t)c * HD) + lane);
        float4 ch = *((const float4*)(h + (size_t)c * HD) + lane);
        ax.x = fmaf(nm, cx.x, ax.x); ax.y = fmaf(nm, cx.y, ax.y);
        ax.z = fmaf(nm, cx.z, ax.z); ax.w = fmaf(nm, cx.w, ax.w);
        ah.x = fmaf(nm, ch.x, ah.x); ah.y = fmaf(nm, ch.y, ah.y);
        ah.z = fmaf(nm, ch.z, ah.z); ah.w = fmaf(nm, ch.w, ah.w);
    }
    ((float4*)(g_ax + (size_t)n * HD))[lane] = ax;
    ((float4*)(g_ah + (size_t)n * HD))[lane] = ah;
}

// ---------------- tensor-core GEMM core (m16n8k16 bf16, 3-term split) ----------------
// block: 256 threads = 8 warps (2 m x 4 n), tile 128x128, K streamed in 2 chunks of 64.
#define MMA_BF16(c, a, bb0, bb1) \
    asm("mma.sync.aligned.m16n8k16.row.col.f32.bf16.bf16.f32 " \
        "{%0,%1,%2,%3},{%4,%5,%6,%7},{%8,%9},{%0,%1,%2,%3};" \
        : "+f"(c[0]), "+f"(c[1]), "+f"(c[2]), "+f"(c[3]) \
        : "r"(a[0]), "r"(a[1]), "r"(a[2]), "r"(a[3]), "r"(bb0), "r"(bb1))

__device__ __forceinline__ void gemm_source(float (*acc)[4][4],
                                            const float* __restrict__ A, int lda,
                                            int stream, int row0,
                                            unsigned* As_hi, unsigned* As_lo) {
    int tid = threadIdx.x;
    int wid = tid >> 5, lane = tid & 31;
    int wm = wid >> 2, wn = wid & 3;
    int m0 = wm * 64, tig = lane & 3, grp = lane >> 2;
    const uint4* __restrict__ Bp = g_Bp + (stream << 12);

    for (int chunk = 0; chunk < 2; chunk++) {
        __syncthreads();
        // stage + split A chunk (128 rows x 64 k) into hi/lo bf16x2-pair arrays
#pragma unroll
        for (int i = 0; i < 8; i++) {
            int f = i * 256 + tid;            // 0..2047
            int row = f >> 4, c4 = (f & 15) * 4;
            float4 v = make_float4(0.f, 0.f, 0.f, 0.f);
            int grow = row0 + row;
            if (grow < NNODES)
                v = *(const float4*)(A + (size_t)grow * lda + chunk * 64 + c4);
            int pc = c4 >> 1;                 // pair column
            unsigned h0, l0, h1, l1;
            bf16_split_pair(v.x, v.y, h0, l0);
            bf16_split_pair(v.z, v.w, h1, l1);
            As_hi[row * ASTRIDE + pc] = h0; As_hi[row * ASTRIDE + pc + 1] = h1;
            As_lo[row * ASTRIDE + pc] = l0; As_lo[row * ASTRIDE + pc + 1] = l1;
        }
        __syncthreads();
#pragma unroll
        for (int ksl = 0; ksl < 4; ksl++) {
            unsigned ahi[4][4], alo[4][4];
#pragma unroll
            for (int mt = 0; mt < 4; mt++) {
                int base = (m0 + mt * 16 + grp) * ASTRIDE + ksl * 8 + tig;
                ahi[mt][0] = As_hi[base];
                ahi[mt][1] = As_hi[base + 8 * ASTRIDE];
                ahi[mt][2] = As_hi[base + 4];
                ahi[mt][3] = As_hi[base + 8 * ASTRIDE + 4];
                alo[mt][0] = As_lo[base];
                alo[mt][1] = As_lo[base + 8 * ASTRIDE];
                alo[mt][2] = As_lo[base + 4];
                alo[mt][3] = As_lo[base + 8 * ASTRIDE + 4];
            }
            int ks = chunk * 4 + ksl;
#pragma unroll
            for (int nt = 0; nt < 4; nt++) {
                uint4 b = Bp[(ks * 16 + wn * 4 + nt) * 32 + lane];
#pragma unroll
                for (int mt = 0; mt < 4; mt++) {
                    float* c = acc[mt][nt];
                    MMA_BF16(c, ahi[mt], b.x, b.y);   // hi*hi
                    MMA_BF16(c, ahi[mt], b.z, b.w);   // hi*lo
                    MMA_BF16(c, alo[mt], b.x, b.y);   // lo*hi
                }
            }
        }
    }
}

template<bool BIASRELU>
__device__ __forceinline__ void gemm_epilogue(float (*acc)[4][4],
                                              const float* __restrict__ bias,
                                              float* __restrict__ C, int ldc, int row0) {
    int tid = threadIdx.x;
    int wid = tid >> 5, lane = tid & 31;
    int wm = wid >> 2, wn = wid & 3;
    int m0 = wm * 64, n0 = wn * 32;
    int tig = lane & 3, grp = lane >> 2;
#pragma unroll
    for (int nt = 0; nt < 4; nt++) {
        int col = n0 + nt * 8 + 2 * tig;
        float b0 = BIASRELU ? bias[col] : 0.f;
        float b1 = BIASRELU ? bias[col + 1] : 0.f;
#pragma unroll
        for (int mt = 0; mt < 4; mt++) {
            int r = row0 + m0 + mt * 16 + grp;
            float* c = acc[mt][nt];
            if (r < NNODES) {
                float u0 = c[0] + b0, u1 = c[1] + b1;
                if (BIASRELU) { u0 = fmaxf(u0, 0.f); u1 = fmaxf(u1, 0.f); }
                *(float2*)&C[(size_t)r * ldc + col] = make_float2(u0, u1);
            }
            int r2 = r + 8;
            if (r2 < NNODES) {
                float u2 = c[2] + b0, u3 = c[3] + b1;
                if (BIASRELU) { u2 = fmaxf(u2, 0.f); u3 = fmaxf(u3, 0.f); }
                *(float2*)&C[(size_t)r2 * ldc + col] = make_float2(u2, u3);
            }
        }
    }
}

// layer 1: z[:, sg*128..] = relu(a_s @ W0[g] + b0[g]), sg = s*4+g
__global__ __launch_bounds__(256) void k_mma1(const float* __restrict__ bx0,
                                              const float* __restrict__ bh0) {
    __shared__ unsigned As_hi[128 * ASTRIDE];
    __shared__ unsigned As_lo[128 * ASTRIDE];
    int sg = blockIdx.y;
    int row0 = blockIdx.x * 128;
    float acc[4][4][4];
#pragma unroll
    for (int a = 0; a < 4; a++)
#pragma unroll
        for (int b = 0; b < 4; b++)
#pragma unroll
            for (int cc = 0; cc < 4; cc++) acc[a][b][cc] = 0.f;
    const float* A = (sg < 4) ? g_ax : g_ah;
    gemm_source(acc, A, 128, sg, row0, As_hi, As_lo);
    const float* bias = ((sg < 4) ? bx0 : bh0) + (sg & 3) * 128;
    gemm_epilogue<true>(acc, bias, g_z + sg * 128, 1024, row0);
}

// layer 2 (pre-prop, NO bias): y[:, g*128..] = z_x[g] @ Wx1[g] + z_h[g] @ Wh1[g]
__global__ __launch_bounds__(256) void k_mma2() {
    __shared__ unsigned As_hi[128 * ASTRIDE];
    __shared__ unsigned As_lo[128 * ASTRIDE];
    int g = blockIdx.y;
    int row0 = blockIdx.x * 128;
    float acc[4][4][4];
#pragma unroll
    for (int a = 0; a < 4; a++)
#pragma unroll
        for (int b = 0; b < 4; b++)
#pragma unroll
            for (int cc = 0; cc < 4; cc++) acc[a][b][cc] = 0.f;
    gemm_source(acc, g_z + g * 128, 1024, 8 + g, row0, As_hi, As_lo);
    gemm_source(acc, g_z + 512 + g * 128, 1024, 12 + g, row0, As_hi, As_lo);
    gemm_epilogue<false>(acc, nullptr, g_y + g * 128, 512, row0);
}

// ---------------- fused F=512 gather + LSTM epilogue: one block (128 thr) per node ----------------
__device__ __forceinline__ float sigmoidf_(float v) { return 1.f / (1.f + expf(-v)); }

__global__ void __launch_bounds__(128) k_gather_lstm(
    const float* __restrict__ c,
    const float* __restrict__ bx1, const float* __restrict__ bh1,
    const float* __restrict__ wc, const float* __restrict__ bg,
    float* __restrict__ out)
{
    __shared__ float sG[512];
    int n = blockIdx.x;
    int t = threadIdx.x;
    float sd = g_dis[n];
    float s2 = sd * sd;
    float4 v = ((const float4*)(g_y + (size_t)n * 512))[t];
    float4 acc = make_float4(s2 * v.x, s2 * v.y, s2 * v.z, s2 * v.w);
    int e0 = g_rowptr[n], e1 = g_rowptr[n + 1];
    for (int e = e0; e < e1; ++e) {
        int cc = g_ecol[e];
        float nm = g_enorm[e];
        float4 yv = ((const float4*)(g_y + (size_t)cc * 512))[t];
        acc.x = fmaf(nm, yv.x, acc.x); acc.y = fmaf(nm, yv.y, acc.y);
        acc.z = fmaf(nm, yv.z, acc.z); acc.w = fmaf(nm, yv.w, acc.w);
    }
    ((float4*)sG)[t] = acc;
    __syncthreads();
    int f = t;
    int idx = n * HD + f;
    float cv = c[idx];
    float Gi = sG[f]       + bx1[f]       + bh1[f];
    float Gf = sG[128 + f] + bx1[128 + f] + bh1[128 + f];
    float Gc = sG[256 + f] + bx1[256 + f] + bh1[256 + f];
    float Go = sG[384 + f] + bx1[384 + f] + bh1[384 + f];
    float I  = sigmoidf_(Gi + wc[f] * cv + bg[f]);
    float Fg = sigmoidf_(Gf + wc[128 + f] * cv + bg[128 + f]);
    float T  = tanhf(Gc + bg[256 + f]);
    float Cn = Fg * cv + I * T;
    float O  = sigmoidf_(Go + wc[256 + f] * Cn + bg[384 + f]);
    float Hn = O * tanhf(Cn);
    out[idx] = Hn;
    out[(size_t)NNODES * HD + idx] = Cn;
}

// ---------------- launch ----------------
extern "C" void kernel_launch(void* const* d_in, const int* in_sizes, int n_in,
                              void* d_out, int out_size) {
    const float* x   = (const float*)d_in[0];
    const void*  ei  = d_in[1];                 // int32 or int64, detected on device
    const float* w   = (const float*)d_in[2];
    const float* h   = (const float*)d_in[3];
    const float* c   = (const float*)d_in[4];
    const float* Wx0 = (const float*)d_in[5];
    const float* bx0 = (const float*)d_in[6];
    const float* Wx1 = (const float*)d_in[7];
    const float* bx1 = (const float*)d_in[8];
    const float* Wh0 = (const float*)d_in[9];
    const float* bh0 = (const float*)d_in[10];
    const float* Wh1 = (const float*)d_in[11];
    const float* bh1 = (const float*)d_in[12];
    const float* wc  = (const float*)d_in[13];
    const float* bg  = (const float*)d_in[14];
    float* out = (float*)d_out;

    const int T = 256;
    // prologue
    k_init<<<(NNODES + T - 1) / T, T>>>((const int*)ei);
    k_wprep<<<(16 * 8 * 16 * 32 + T - 1) / T, T>>>(Wx0, Wh0, Wx1, Wh1);
    k_edge_prep<<<(NEDGES + T - 1) / T, T>>>(ei, w);
    k_scan<<<1, 1024>>>();
    k_scatter<<<(NEDGES + T - 1) / T, T>>>(w);

    // fused first props (F=128) for x and h, gather-based
    k_gather_xh<<<(NNODES * 32 + T - 1) / T, T>>>(x, h);

    // tensor-core GEMMs (bf16 3-term split)
    dim3 g1((NNODES + 127) / 128, 8);
    k_mma1<<<g1, 256>>>(bx0, bh0);
    dim3 g2((NNODES + 127) / 128, 4);
    k_mma2<<<g2, 256>>>();

    // fused F=512 gather + LSTM epilogue
    k_gather_lstm<<<NNODES, 128>>>(c, bx1, bh1, wc, bg, out);
}

// round 7
// speedup vs baseline: 4.4813x; 1.1039x over previous
#include <cuda_runtime.h>
#include <math.h>

#define NNODES 20000
#define NEDGES 320000
#define HD 128
#define FSTR 68          // pair-column stride for full-K staging (conflict-free)
#define NPB 1000         // nodes per scan block
#define NSB 20           // scan blocks

// ---------------- scratch (static device allocations) ----------------
__device__ int   g_is64;
__device__ __align__(16) float g_deg[NNODES];
__device__ __align__(16) int   g_cnt[NNODES];
__device__ __align__(16) int   g_bsum[NSB];
__device__ __align__(16) int   g_rowptr[NNODES + 4];
__device__ __align__(16) int   g_cur[NNODES + 4];
__device__ __align__(16) float g_dis[NNODES];
__device__ __align__(16) int   g_src[NEDGES];
__device__ __align__(16) int   g_dst[NEDGES];
__device__ __align__(16) int   g_ecol[NEDGES];    // CSR (by dst): src node
__device__ __align__(16) float g_enorm[NEDGES];   // CSR (by dst): edge norm
__device__ __align__(16) float g_ax[(size_t)NNODES * HD];   // prop(x)
__device__ __align__(16) float g_ah[(size_t)NNODES * HD];   // prop(h)
__device__ __align__(16) float g_z[(size_t)NNODES * 1024];  // relu layer-1: [N][x gates | h gates]
__device__ __align__(16) float g_y[(size_t)NNODES * 512];   // pre-prop gate features
// pre-split bf16 weights: [stream 16][ks 8][nt 16][lane 32] = (hi0,hi1,lo0,lo1)
__device__ __align__(16) uint4 g_Bp[16 * 8 * 16 * 32];

// bf16 truncation split of a k-pair (x0=even k, x1=odd k) into packed bf16x2 regs.
__device__ __forceinline__ void bf16_split_pair(float x0, float x1,
                                                unsigned &hi, unsigned &lo) {
    unsigned b0 = __float_as_uint(x0), b1 = __float_as_uint(x1);
    hi = __byte_perm(b0, b1, 0x7632);              // {lo16=top16(x0), hi16=top16(x1)}
    float l0 = x0 - __uint_as_float(b0 & 0xFFFF0000u);
    float l1 = x1 - __uint_as_float(b1 & 0xFFFF0000u);
    asm("cvt.rn.bf16x2.f32 %0, %1, %2;" : "=r"(lo) : "f"(l1), "f"(l0));
}

// ---------------- init deg/cnt + edge dtype detect (block 0) ----------------
__global__ void k_init(const int* __restrict__ ei32) {
    int i = blockIdx.x * blockDim.x + threadIdx.x;
    if (i < NNODES) { g_deg[i] = 1.0f; g_cnt[i] = 0; }   // self-loop weight 1
    if (blockIdx.x == 0) {
        __shared__ int nz;
        if (threadIdx.x == 0) nz = 0;
        __syncthreads();
        if (threadIdx.x < 128) {
            if (ei32[2 * threadIdx.x + 1] != 0) atomicAdd(&nz, 1);
        }
        __syncthreads();
        if (threadIdx.x == 0) g_is64 = (nz == 0) ? 1 : 0;
    }
}

// ---------------- edge decode + histograms ----------------
__global__ void k_edge_prep(const void* __restrict__ ei_raw,
                            const float* __restrict__ w) {
    int e = blockIdx.x * blockDim.x + threadIdx.x;
    if (e >= NEDGES) return;
    int s, d;
    if (g_is64) {
        const long long* ei = (const long long*)ei_raw;
        s = (int)ei[e];
        d = (int)ei[NEDGES + e];
    } else {
        const int* ei = (const int*)ei_raw;
        s = ei[e];
        d = ei[NEDGES + e];
    }
    if ((unsigned)s >= NNODES) s = 0;
    if ((unsigned)d >= NNODES) d = 0;
    g_src[e] = s;
    g_dst[e] = d;
    atomicAdd(&g_deg[d], w[e]);
    atomicAdd(&g_cnt[d], 1);
}

// ---------------- parallel scan phase 1: block sums + dis ----------------
__global__ void k_scan1() {          // grid NSB x 1024
    int b = blockIdx.x, t = threadIdx.x;
    int base = b * NPB;
    int v = (t < NPB) ? g_cnt[base + t] : 0;
    // block reduce
    int s = v;
#pragma unroll
    for (int off = 16; off > 0; off >>= 1) s += __shfl_down_sync(0xFFFFFFFFu, s, off);
    __shared__ int wsum[32];
    int lane = t & 31, wid = t >> 5;
    if (lane == 0) wsum[wid] = s;
    __syncthreads();
    if (wid == 0) {
        int x = wsum[lane];
#pragma unroll
        for (int off = 16; off > 0; off >>= 1) x += __shfl_down_sync(0xFFFFFFFFu, x, off);
        if (lane == 0) g_bsum[b] = x;
    }
    // dis = deg^-1/2
    if (t < NPB) {
        float dg = g_deg[base + t];
        g_dis[base + t] = dg > 0.f ? rsqrtf(fmaxf(dg, 1e-12f)) : 0.f;
    }
}

// ---------------- parallel scan phase 2: write rowptr/cur ----------------
__global__ void k_scan2() {          // grid NSB x 1024
    int b = blockIdx.x, t = threadIdx.x;
    int lane = t & 31, wid = t >> 5;
    __shared__ int sbase;
    __shared__ int wsum[32];
    if (wid == 0) {
        int x = (lane < b) ? g_bsum[lane] : 0;
#pragma unroll
        for (int off = 16; off > 0; off >>= 1) x += __shfl_down_sync(0xFFFFFFFFu, x, off);
        if (lane == 0) sbase = x;
    }
    int base = b * NPB;
    int v = (t < NPB) ? g_cnt[base + t] : 0;
    int incl = v;
#pragma unroll
    for (int off = 1; off < 32; off <<= 1) {
        int n = __shfl_up_sync(0xFFFFFFFFu, incl, off);
        if (lane >= off) incl += n;
    }
    if (lane == 31) wsum[wid] = incl;
    __syncthreads();
    if (wid == 0) {
        int wv = wsum[lane];
        int wi = wv;
#pragma unroll
        for (int off = 1; off < 32; off <<= 1) {
            int n = __shfl_up_sync(0xFFFFFFFFu, wi, off);
            if (lane >= off) wi += n;
        }
        wsum[lane] = wi - wv;   // exclusive warp base
    }
    __syncthreads();
    if (t < NPB) {
        int excl = sbase + wsum[wid] + incl - v;
        g_rowptr[base + t] = excl;
        g_cur[base + t] = excl;
    }
    if (b == NSB - 1 && t == 0) g_rowptr[NNODES] = NEDGES;
}

// ---------------- scatter edges into CSR + compute norm ----------------
__global__ void k_scatter(const float* __restrict__ w) {
    int e = blockIdx.x * blockDim.x + threadIdx.x;
    if (e >= NEDGES) return;
    int s = g_src[e];
    int d = g_dst[e];
    int pos = atomicAdd(&g_cur[d], 1);
    g_ecol[pos] = s;
    g_enorm[pos] = g_dis[s] * w[e] * g_dis[d];
}

// ---------------- weight prep: bf16 hi/lo split, B-fragment order (m16n8k16) ----------------
// streams: 0-3 Wx0[g], 4-7 Wh0[g], 8-11 Wx1[g], 12-15 Wh1[g]
__global__ void k_wprep(const float* __restrict__ Wx0, const float* __restrict__ Wh0,
                        const float* __restrict__ Wx1, const float* __restrict__ Wh1) {
    int idx = blockIdx.x * blockDim.x + threadIdx.x;    // 16*8*16*32 = 65536
    if (idx >= 16 * 8 * 16 * 32) return;
    int s    = idx >> 12;          // stream
    int ks   = (idx >> 9) & 7;     // k-step (k0 = ks*16)
    int nt   = (idx >> 5) & 15;    // n-tile (n0 = nt*8)
    int lane = idx & 31;
    const float* W;
    if (s < 4)       W = Wx0 + s * 16384;
    else if (s < 8)  W = Wh0 + (s - 4) * 16384;
    else if (s < 12) W = Wx1 + (s - 8) * 16384;
    else             W = Wh1 + (s - 12) * 16384;
    int tig = lane & 3, grp = lane >> 2;
    int k0 = ks * 16, n = nt * 8 + grp;
    float w0 = W[(k0 + 2 * tig)     * 128 + n];
    float w1 = W[(k0 + 2 * tig + 1) * 128 + n];
    float w2 = W[(k0 + 2 * tig + 8) * 128 + n];
    float w3 = W[(k0 + 2 * tig + 9) * 128 + n];
    unsigned h0, l0, h1, l1;
    bf16_split_pair(w0, w1, h0, l0);
    bf16_split_pair(w2, w3, h1, l1);
    g_Bp[idx] = make_uint4(h0, h1, l0, l1);
}

// ---------------- fused gather SpMM for x and h (F=128), one warp per node ----------------
__global__ void k_gather_xh(const float* __restrict__ x, const float* __restrict__ h) {
    int warp = (blockIdx.x * blockDim.x + threadIdx.x) >> 5;
    int lane = threadIdx.x & 31;
    if (warp >= NNODES) return;
    int n = warp;
    float sd = g_dis[n];
    float s2 = sd * sd;
    float4 xv = *((const float4*)(x + (size_t)n * HD) + lane);
    float4 hv = *((const float4*)(h + (size_t)n * HD) + lane);
    float4 ax = make_float4(s2 * xv.x, s2 * xv.y, s2 * xv.z, s2 * xv.w);
    float4 ah = make_float4(s2 * hv.x, s2 * hv.y, s2 * hv.z, s2 * hv.w);
    int e0 = g_rowptr[n], e1 = g_rowptr[n + 1];
#pragma unroll 4
    for (int e = e0; e < e1; ++e) {
        int c = g_ecol[e];
        float nm = g_enorm[e];
        float4 cx = *((const float4*)(x + (size_t)c * HD) + lane);
        float4 ch = *((const float4*)(h + (size_t)c * HD) + lane);
        ax.x = fmaf(nm, cx.x, ax.x); ax.y = fmaf(nm, cx.y, ax.y);
        ax.z = fmaf(nm, cx.z, ax.z); ax.w = fmaf(nm, cx.w, ax.w);
        ah.x = fmaf(nm, ch.x, ah.x); ah.y = fmaf(nm, ch.y, ah.y);
        ah.z = fmaf(nm, ch.z, ah.z); ah.w = fmaf(nm, ch.w, ah.w);
    }
    ((float4*)(g_ax + (size_t)n * HD))[lane] = ax;
    ((float4*)(g_ah + (size_t)n * HD))[lane] = ah;
}

// ---------------- tensor-core GEMM core (m16n8k16 bf16, 3-term split) ----------------
// block: 256 threads = 8 warps (2 m x 4 n), tile 128x128, full-K staging in dyn smem.
#define MMA_BF16(c, a, bb0, bb1) \
    asm("mma.sync.aligned.m16n8k16.row.col.f32.bf16.bf16.f32 " \
        "{%0,%1,%2,%3},{%4,%5,%6,%7},{%8,%9},{%0,%1,%2,%3};" \
        : "+f"(c[0]), "+f"(c[1]), "+f"(c[2]), "+f"(c[3]) \
        : "r"(a[0]), "r"(a[1]), "r"(a[2]), "r"(a[3]), "r"(bb0), "r"(bb1))

#define SMEM_MMA_BYTES (2 * 128 * FSTR * 4)

__device__ __forceinline__ void gemm_source(float (*acc)[4][4],
                                            const float* __restrict__ A, int lda,
                                            int stream, int row0,
                                            unsigned* As_hi, unsigned* As_lo) {
    int tid = threadIdx.x;
    int wid = tid >> 5, lane = tid & 31;
    int wm = wid >> 2, wn = wid & 3;
    int m0 = wm * 64, tig = lane & 3, grp = lane >> 2;
    const uint4* __restrict__ Bp = g_Bp + (stream << 12);

    __syncthreads();
    // stage + split whole 128x128 A tile: 16 float4 per thread, issued up-front
    float4 v[16];
#pragma unroll
    for (int i = 0; i < 16; i++) {
        int f = i * 256 + tid;            // 0..4095
        int row = f >> 5;                 // 0..127
        int c4 = (f & 31) * 4;            // 0..124
        int grow = row0 + row;
        v[i] = (grow < NNODES) ? *(const float4*)(A + (size_t)grow * lda + c4)
                               : make_float4(0.f, 0.f, 0.f, 0.f);
    }
#pragma unroll
    for (int i = 0; i < 16; i++) {
        int f = i * 256 + tid;
        int row = f >> 5;
        int pc = (f & 31) * 2;            // pair column 0..62 (even)
        unsigned h0, l0, h1, l1;
        bf16_split_pair(v[i].x, v[i].y, h0, l0);
        bf16_split_pair(v[i].z, v[i].w, h1, l1);
        As_hi[row * FSTR + pc] = h0; As_hi[row * FSTR + pc + 1] = h1;
        As_lo[row * FSTR + pc] = l0; As_lo[row * FSTR + pc + 1] = l1;
    }
    __syncthreads();
#pragma unroll
    for (int ks = 0; ks < 8; ks++) {
        unsigned ahi[4][4], alo[4][4];
#pragma unroll
        for (int mt = 0; mt < 4; mt++) {
            int base = (m0 + mt * 16 + grp) * FSTR + ks * 8 + tig;
            ahi[mt][0] = As_hi[base];
            ahi[mt][1] = As_hi[base + 8 * FSTR];
            ahi[mt][2] = As_hi[base + 4];
            ahi[mt][3] = As_hi[base + 8 * FSTR + 4];
            alo[mt][0] = As_lo[base];
            alo[mt][1] = As_lo[base + 8 * FSTR];
            alo[mt][2] = As_lo[base + 4];
            alo[mt][3] = As_lo[base + 8 * FSTR + 4];
        }
#pragma unroll
        for (int nt = 0; nt < 4; nt++) {
            uint4 b = Bp[(ks * 16 + wn * 4 + nt) * 32 + lane];
#pragma unroll
            for (int mt = 0; mt < 4; mt++) {
                float* c = acc[mt][nt];
                MMA_BF16(c, ahi[mt], b.x, b.y);   // hi*hi
                MMA_BF16(c, ahi[mt], b.z, b.w);   // hi*lo
                MMA_BF16(c, alo[mt], b.x, b.y);   // lo*hi
            }
        }
    }
}

template<bool BIASRELU>
__device__ __forceinline__ void gemm_epilogue(float (*acc)[4][4],
                                              const float* __restrict__ bias,
                                              float* __restrict__ C, int ldc, int row0) {
    int tid = threadIdx.x;
    int wid = tid >> 5, lane = tid & 31;
    int wm = wid >> 2, wn = wid & 3;
    int m0 = wm * 64, n0 = wn * 32;
    int tig = lane & 3, grp = lane >> 2;
#pragma unroll
    for (int nt = 0; nt < 4; nt++) {
        int col = n0 + nt * 8 + 2 * tig;
        float b0 = BIASRELU ? bias[col] : 0.f;
        float b1 = BIASRELU ? bias[col + 1] : 0.f;
#pragma unroll
        for (int mt = 0; mt < 4; mt++) {
            int r = row0 + m0 + mt * 16 + grp;
            float* c = acc[mt][nt];
            if (r < NNODES) {
                float u0 = c[0] + b0, u1 = c[1] + b1;
                if (BIASRELU) { u0 = fmaxf(u0, 0.f); u1 = fmaxf(u1, 0.f); }
                *(float2*)&C[(size_t)r * ldc + col] = make_float2(u0, u1);
            }
            int r2 = r + 8;
            if (r2 < NNODES) {
                float u2 = c[2] + b0, u3 = c[3] + b1;
                if (BIASRELU) { u2 = fmaxf(u2, 0.f); u3 = fmaxf(u3, 0.f); }
                *(float2*)&C[(size_t)r2 * ldc + col] = make_float2(u2, u3);
            }
        }
    }
}

// layer 1: z[:, sg*128..] = relu(a_s @ W0[g] + b0[g]), sg = s*4+g
__global__ __launch_bounds__(256) void k_mma1(const float* __restrict__ bx0,
                                              const float* __restrict__ bh0) {
    extern __shared__ unsigned smem_u[];
    unsigned* As_hi = smem_u;
    unsigned* As_lo = smem_u + 128 * FSTR;
    int sg = blockIdx.y;
    int row0 = blockIdx.x * 128;
    float acc[4][4][4];
#pragma unroll
    for (int a = 0; a < 4; a++)
#pragma unroll
        for (int b = 0; b < 4; b++)
#pragma unroll
            for (int cc = 0; cc < 4; cc++) acc[a][b][cc] = 0.f;
    const float* A = (sg < 4) ? g_ax : g_ah;
    gemm_source(acc, A, 128, sg, row0, As_hi, As_lo);
    const float* bias = ((sg < 4) ? bx0 : bh0) + (sg & 3) * 128;
    gemm_epilogue<true>(acc, bias, g_z + sg * 128, 1024, row0);
}

// layer 2 (pre-prop, NO bias): y[:, g*128..] = z_x[g] @ Wx1[g] + z_h[g] @ Wh1[g]
__global__ __launch_bounds__(256) void k_mma2() {
    extern __shared__ unsigned smem_u[];
    unsigned* As_hi = smem_u;
    unsigned* As_lo = smem_u + 128 * FSTR;
    int g = blockIdx.y;
    int row0 = blockIdx.x * 128;
    float acc[4][4][4];
#pragma unroll
    for (int a = 0; a < 4; a++)
#pragma unroll
        for (int b = 0; b < 4; b++)
#pragma unroll
            for (int cc = 0; cc < 4; cc++) acc[a][b][cc] = 0.f;
    gemm_source(acc, g_z + g * 128, 1024, 8 + g, row0, As_hi, As_lo);
    gemm_source(acc, g_z + 512 + g * 128, 1024, 12 + g, row0, As_hi, As_lo);
    gemm_epilogue<false>(acc, nullptr, g_y + g * 128, 512, row0);
}

// ---------------- fused F=512 gather + LSTM epilogue: one block (128 thr) per node ----------------
__device__ __forceinline__ float sigmoidf_(float v) { return 1.f / (1.f + expf(-v)); }

__global__ void __launch_bounds__(128) k_gather_lstm(
    const float* __restrict__ c,
    const float* __restrict__ bx1, const float* __restrict__ bh1,
    const float* __restrict__ wc, const float* __restrict__ bg,
    float* __restrict__ out)
{
    __shared__ float sG[512];
    int n = blockIdx.x;
    int t = threadIdx.x;
    float sd = g_dis[n];
    float s2 = sd * sd;
    float4 v = ((const float4*)(g_y + (size_t)n * 512))[t];
    float4 acc = make_float4(s2 * v.x, s2 * v.y, s2 * v.z, s2 * v.w);
    int e0 = g_rowptr[n], e1 = g_rowptr[n + 1];
#pragma unroll 4
    for (int e = e0; e < e1; ++e) {
        int cc = g_ecol[e];
        float nm = g_enorm[e];
        float4 yv = ((const float4*)(g_y + (size_t)cc * 512))[t];
        acc.x = fmaf(nm, yv.x, acc.x); acc.y = fmaf(nm, yv.y, acc.y);
        acc.z = fmaf(nm, yv.z, acc.z); acc.w = fmaf(nm, yv.w, acc.w);
    }
    ((float4*)sG)[t] = acc;
    __syncthreads();
    int f = t;
    int idx = n * HD + f;
    float cv = c[idx];
    float Gi = sG[f]       + bx1[f]       + bh1[f];
    float Gf = sG[128 + f] + bx1[128 + f] + bh1[128 + f];
    float Gc = sG[256 + f] + bx1[256 + f] + bh1[256 + f];
    float Go = sG[384 + f] + bx1[384 + f] + bh1[384 + f];
    float I  = sigmoidf_(Gi + wc[f] * cv + bg[f]);
    float Fg = sigmoidf_(Gf + wc[128 + f] * cv + bg[128 + f]);
    float T  = tanhf(Gc + bg[256 + f]);
    float Cn = Fg * cv + I * T;
    float O  = sigmoidf_(Go + wc[256 + f] * Cn + bg[384 + f]);
    float Hn = O * tanhf(Cn);
    out[idx] = Hn;
    out[(size_t)NNODES * HD + idx] = Cn;
}

// ---------------- launch ----------------
extern "C" void kernel_launch(void* const* d_in, const int* in_sizes, int n_in,
                              void* d_out, int out_size) {
    const float* x   = (const float*)d_in[0];
    const void*  ei  = d_in[1];                 // int32 or int64, detected on device
    const float* w   = (const float*)d_in[2];
    const float* h   = (const float*)d_in[3];
    const float* c   = (const float*)d_in[4];
    const float* Wx0 = (const float*)d_in[5];
    const float* bx0 = (const float*)d_in[6];
    const float* Wx1 = (const float*)d_in[7];
    const float* bx1 = (const float*)d_in[8];
    const float* Wh0 = (const float*)d_in[9];
    const float* bh0 = (const float*)d_in[10];
    const float* Wh1 = (const float*)d_in[11];
    const float* bh1 = (const float*)d_in[12];
    const float* wc  = (const float*)d_in[13];
    const float* bg  = (const float*)d_in[14];
    float* out = (float*)d_out;

    static int smem_set = 0;
    if (!smem_set) {
        cudaFuncSetAttribute(k_mma1, cudaFuncAttributeMaxDynamicSharedMemorySize, SMEM_MMA_BYTES);
        cudaFuncSetAttribute(k_mma2, cudaFuncAttributeMaxDynamicSharedMemorySize, SMEM_MMA_BYTES);
        smem_set = 1;
    }

    const int T = 256;
    // prologue
    k_init<<<(NNODES + T - 1) / T, T>>>((const int*)ei);
    k_wprep<<<(16 * 8 * 16 * 32 + T - 1) / T, T>>>(Wx0, Wh0, Wx1, Wh1);
    k_edge_prep<<<(NEDGES + T - 1) / T, T>>>(ei, w);
    k_scan1<<<NSB, 1024>>>();
    k_scan2<<<NSB, 1024>>>();
    k_scatter<<<(NEDGES + T - 1) / T, T>>>(w);

    // fused first props (F=128) for x and h, gather-based
    k_gather_xh<<<(NNODES * 32 + T - 1) / T, T>>>(x, h);

    // tensor-core GEMMs (bf16 3-term split, full-K staging)
    dim3 g1((NNODES + 127) / 128, 8);
    k_mma1<<<g1, 256, SMEM_MMA_BYTES>>>(bx0, bh0);
    dim3 g2((NNODES + 127) / 128, 4);
    k_mma2<<<g2, 256, SMEM_MMA_BYTES>>>();

    // fused F=512 gather + LSTM epilogue
    k_gather_lstm<<<NNODES, 128>>>(c, bx1, bh1, wc, bg, out);
}

// round 8
// speedup vs baseline: 4.8853x; 1.0902x over previous
#include <cuda_runtime.h>
#include <math.h>

#define NNODES 20000
#define NEDGES 320000
#define HD 128
#define FSTR 68                  // pair-column stride (words), conflict-free
#define ZOFF (128 * FSTR)        // words per hi/lo array
#define SMEM_FUSED_BYTES (6 * ZOFF * 4)   // As + zx + zh, hi+lo each = 208896 B
#define NPB 1000                 // nodes per scan block
#define NSB 20                   // scan blocks

// ---------------- scratch (static device allocations) ----------------
__device__ int   g_is64;
__device__ __align__(16) float g_deg[NNODES];
__device__ __align__(16) int   g_cnt[NNODES];
__device__ __align__(16) int   g_bsum[NSB];
__device__ __align__(16) int   g_rowptr[NNODES + 4];
__device__ __align__(16) int   g_cur[NNODES + 4];
__device__ __align__(16) float g_dis[NNODES];
__device__ __align__(16) int   g_ecol[NEDGES];    // CSR (by dst): src node
__device__ __align__(16) float g_enorm[NEDGES];   // CSR (by dst): edge norm
__device__ __align__(16) float g_ax[(size_t)NNODES * HD];   // prop(x)
__device__ __align__(16) float g_ah[(size_t)NNODES * HD];   // prop(h)
__device__ __align__(16) float g_y[(size_t)NNODES * 512];   // pre-prop gate features
// pre-split bf16 weights: [stream 16][ks 8][nt 16][lane 32] = (hi0,hi1,lo0,lo1)
__device__ __align__(16) uint4 g_Bp[16 * 8 * 16 * 32];

// bf16 truncation split of a k-pair (x0=even k, x1=odd k) into packed bf16x2 regs.
__device__ __forceinline__ void bf16_split_pair(float x0, float x1,
                                                unsigned &hi, unsigned &lo) {
    unsigned b0 = __float_as_uint(x0), b1 = __float_as_uint(x1);
    hi = __byte_perm(b0, b1, 0x7632);              // {lo16=top16(x0), hi16=top16(x1)}
    float l0 = x0 - __uint_as_float(b0 & 0xFFFF0000u);
    float l1 = x1 - __uint_as_float(b1 & 0xFFFF0000u);
    asm("cvt.rn.bf16x2.f32 %0, %1, %2;" : "=r"(lo) : "f"(l1), "f"(l0));
}

// ---------------- init deg/cnt + edge dtype detect (block 0) ----------------
__global__ void k_init(const int* __restrict__ ei32) {
    int i = blockIdx.x * blockDim.x + threadIdx.x;
    if (i < NNODES) { g_deg[i] = 1.0f; g_cnt[i] = 0; }   // self-loop weight 1
    if (blockIdx.x == 0) {
        __shared__ int nz;
        if (threadIdx.x == 0) nz = 0;
        __syncthreads();
        if (threadIdx.x < 128) {
            if (ei32[2 * threadIdx.x + 1] != 0) atomicAdd(&nz, 1);
        }
        __syncthreads();
        if (threadIdx.x == 0) g_is64 = (nz == 0) ? 1 : 0;
    }
}

// ---------------- edge decode ----------------
__device__ __forceinline__ void edge_decode(const void* __restrict__ ei_raw, int e,
                                            int &s, int &d) {
    if (g_is64) {
        const long long* ei = (const long long*)ei_raw;
        s = (int)ei[e];
        d = (int)ei[NEDGES + e];
    } else {
        const int* ei = (const int*)ei_raw;
        s = ei[e];
        d = ei[NEDGES + e];
    }
    if ((unsigned)s >= NNODES) s = 0;
    if ((unsigned)d >= NNODES) d = 0;
}

// ---------------- edge histograms ----------------
__global__ void k_edge_prep(const void* __restrict__ ei_raw,
                            const float* __restrict__ w) {
    int e = blockIdx.x * blockDim.x + threadIdx.x;
    if (e >= NEDGES) return;
    int s, d;
    edge_decode(ei_raw, e, s, d);
    atomicAdd(&g_deg[d], w[e]);
    atomicAdd(&g_cnt[d], 1);
}

// ---------------- parallel scan phase 1: block sums + dis ----------------
__global__ void k_scan1() {          // grid NSB x 1024
    int b = blockIdx.x, t = threadIdx.x;
    int base = b * NPB;
    int v = (t < NPB) ? g_cnt[base + t] : 0;
    int s = v;
#pragma unroll
    for (int off = 16; off > 0; off >>= 1) s += __shfl_down_sync(0xFFFFFFFFu, s, off);
    __shared__ int wsum[32];
    int lane = t & 31, wid = t >> 5;
    if (lane == 0) wsum[wid] = s;
    __syncthreads();
    if (wid == 0) {
        int x = wsum[lane];
#pragma unroll
        for (int off = 16; off > 0; off >>= 1) x += __shfl_down_sync(0xFFFFFFFFu, x, off);
        if (lane == 0) g_bsum[b] = x;
    }
    if (t < NPB) {
        float dg = g_deg[base + t];
        g_dis[base + t] = dg > 0.f ? rsqrtf(fmaxf(dg, 1e-12f)) : 0.f;
    }
}

// ---------------- parallel scan phase 2: write rowptr/cur ----------------
__global__ void k_scan2() {          // grid NSB x 1024
    int b = blockIdx.x, t = threadIdx.x;
    int lane = t & 31, wid = t >> 5;
    __shared__ int sbase;
    __shared__ int wsum[32];
    if (wid == 0) {
        int x = (lane < b) ? g_bsum[lane] : 0;
#pragma unroll
        for (int off = 16; off > 0; off >>= 1) x += __shfl_down_sync(0xFFFFFFFFu, x, off);
        if (lane == 0) sbase = x;
    }
    int base = b * NPB;
    int v = (t < NPB) ? g_cnt[base + t] : 0;
    int incl = v;
#pragma unroll
    for (int off = 1; off < 32; off <<= 1) {
        int n = __shfl_up_sync(0xFFFFFFFFu, incl, off);
        if (lane >= off) incl += n;
    }
    if (lane == 31) wsum[wid] = incl;
    __syncthreads();
    if (wid == 0) {
        int wv = wsum[lane];
        int wi = wv;
#pragma unroll
        for (int off = 1; off < 32; off <<= 1) {
            int n = __shfl_up_sync(0xFFFFFFFFu, wi, off);
            if (lane >= off) wi += n;
        }
        wsum[lane] = wi - wv;   // exclusive warp base
    }
    __syncthreads();
    if (t < NPB) {
        int excl = sbase + wsum[wid] + incl - v;
        g_rowptr[base + t] = excl;
        g_cur[base + t] = excl;
    }
    if (b == NSB - 1 && t == 0) g_rowptr[NNODES] = NEDGES;
}

// ---------------- scatter edges into CSR + compute norm ----------------
__global__ void k_scatter(const void* __restrict__ ei_raw, const float* __restrict__ w) {
    int e = blockIdx.x * blockDim.x + threadIdx.x;
    if (e >= NEDGES) return;
    int s, d;
    edge_decode(ei_raw, e, s, d);
    int pos = atomicAdd(&g_cur[d], 1);
    g_ecol[pos] = s;
    g_enorm[pos] = g_dis[s] * w[e] * g_dis[d];
}

// ---------------- weight prep: bf16 hi/lo split, B-fragment order (m16n8k16) ----------------
// streams: 0-3 Wx0[g], 4-7 Wh0[g], 8-11 Wx1[g], 12-15 Wh1[g]
__global__ void k_wprep(const float* __restrict__ Wx0, const float* __restrict__ Wh0,
                        const float* __restrict__ Wx1, const float* __restrict__ Wh1) {
    int idx = blockIdx.x * blockDim.x + threadIdx.x;    // 16*8*16*32 = 65536
    if (idx >= 16 * 8 * 16 * 32) return;
    int s    = idx >> 12;          // stream
    int ks   = (idx >> 9) & 7;     // k-step (k0 = ks*16)
    int nt   = (idx >> 5) & 15;    // n-tile (n0 = nt*8)
    int lane = idx & 31;
    const float* W;
    if (s < 4)       W = Wx0 + s * 16384;
    else if (s < 8)  W = Wh0 + (s - 4) * 16384;
    else if (s < 12) W = Wx1 + (s - 8) * 16384;
    else             W = Wh1 + (s - 12) * 16384;
    int tig = lane & 3, grp = lane >> 2;
    int k0 = ks * 16, n = nt * 8 + grp;
    float w0 = W[(k0 + 2 * tig)     * 128 + n];
    float w1 = W[(k0 + 2 * tig + 1) * 128 + n];
    float w2 = W[(k0 + 2 * tig + 8) * 128 + n];
    float w3 = W[(k0 + 2 * tig + 9) * 128 + n];
    unsigned h0, l0, h1, l1;
    bf16_split_pair(w0, w1, h0, l0);
    bf16_split_pair(w2, w3, h1, l1);
    g_Bp[idx] = make_uint4(h0, h1, l0, l1);
}

// ---------------- fused gather SpMM for x and h (F=128), one warp per node ----------------
__global__ void k_gather_xh(const float* __restrict__ x, const float* __restrict__ h) {
    int warp = (blockIdx.x * blockDim.x + threadIdx.x) >> 5;
    int lane = threadIdx.x & 31;
    if (warp >= NNODES) return;
    int n = warp;
    float sd = g_dis[n];
    float s2 = sd * sd;
    float4 xv = *((const float4*)(x + (size_t)n * HD) + lane);
    float4 hv = *((const float4*)(h + (size_t)n * HD) + lane);
    float4 ax = make_float4(s2 * xv.x, s2 * xv.y, s2 * xv.z, s2 * xv.w);
    float4 ah = make_float4(s2 * hv.x, s2 * hv.y, s2 * hv.z, s2 * hv.w);
    int e0 = g_rowptr[n], e1 = g_rowptr[n + 1];
#pragma unroll 4
    for (int e = e0; e < e1; ++e) {
        int c = g_ecol[e];
        float nm = g_enorm[e];
        float4 cx = *((const float4*)(x + (size_t)c * HD) + lane);
        float4 ch = *((const float4*)(h + (size_t)c * HD) + lane);
        ax.x = fmaf(nm, cx.x, ax.x); ax.y = fmaf(nm, cx.y, ax.y);
        ax.z = fmaf(nm, cx.z, ax.z); ax.w = fmaf(nm, cx.w, ax.w);
        ah.x = fmaf(nm, ch.x, ah.x); ah.y = fmaf(nm, ch.y, ah.y);
        ah.z = fmaf(nm, ch.z, ah.z); ah.w = fmaf(nm, ch.w, ah.w);
    }
    ((float4*)(g_ax + (size_t)n * HD))[lane] = ax;
    ((float4*)(g_ah + (size_t)n * HD))[lane] = ah;
}

// ---------------- tensor-core GEMM building blocks (m16n8k16 bf16, 3-term split) ----------------
#define MMA_BF16(c, a, bb0, bb1) \
    asm("mma.sync.aligned.m16n8k16.row.col.f32.bf16.bf16.f32 " \
        "{%0,%1,%2,%3},{%4,%5,%6,%7},{%8,%9},{%0,%1,%2,%3};" \
        : "+f"(c[0]), "+f"(c[1]), "+f"(c[2]), "+f"(c[3]) \
        : "r"(a[0]), "r"(a[1]), "r"(a[2]), "r"(a[3]), "r"(bb0), "r"(bb1))

// stage a 128x128 fp32 tile from global, split into hi/lo bf16x2-pair smem arrays
__device__ __forceinline__ void stage_split(const float* __restrict__ A, int lda, int row0,
                                            unsigned* hi_arr, unsigned* lo_arr) {
    int tid = threadIdx.x;
    float4 v[16];
#pragma unroll
    for (int i = 0; i < 16; i++) {
        int f = i * 256 + tid;            // 0..4095
        int row = f >> 5;                 // 0..127
        int c4 = (f & 31) * 4;            // 0..124
        int grow = row0 + row;
        v[i] = (grow < NNODES) ? *(const float4*)(A + (size_t)grow * lda + c4)
                               : make_float4(0.f, 0.f, 0.f, 0.f);
    }
#pragma unroll
    for (int i = 0; i < 16; i++) {
        int f = i * 256 + tid;
        int row = f >> 5;
        int pc = (f & 31) * 2;            // pair column (even)
        unsigned h0, l0, h1, l1;
        bf16_split_pair(v[i].x, v[i].y, h0, l0);
        bf16_split_pair(v[i].z, v[i].w, h1, l1);
        hi_arr[row * FSTR + pc] = h0; hi_arr[row * FSTR + pc + 1] = h1;
        lo_arr[row * FSTR + pc] = l0; lo_arr[row * FSTR + pc + 1] = l1;
    }
}

// acc += (smem A tile) @ (pre-split B stream), 3-term split
__device__ __forceinline__ void mma_pass(float (*acc)[4][4],
                                         const unsigned* As_hi, const unsigned* As_lo,
                                         int stream) {
    int tid = threadIdx.x;
    int wid = tid >> 5, lane = tid & 31;
    int wm = wid >> 2, wn = wid & 3;
    int m0 = wm * 64, tig = lane & 3, grp = lane >> 2;
    const uint4* __restrict__ Bp = g_Bp + (stream << 12);
#pragma unroll
    for (int ks = 0; ks < 8; ks++) {
        unsigned ahi[4][4], alo[4][4];
#pragma unroll
        for (int mt = 0; mt < 4; mt++) {
            int base = (m0 + mt * 16 + grp) * FSTR + ks * 8 + tig;
            ahi[mt][0] = As_hi[base];
            ahi[mt][1] = As_hi[base + 8 * FSTR];
            ahi[mt][2] = As_hi[base + 4];
            ahi[mt][3] = As_hi[base + 8 * FSTR + 4];
            alo[mt][0] = As_lo[base];
            alo[mt][1] = As_lo[base + 8 * FSTR];
            alo[mt][2] = As_lo[base + 4];
            alo[mt][3] = As_lo[base + 8 * FSTR + 4];
        }
#pragma unroll
        for (int nt = 0; nt < 4; nt++) {
            uint4 b = Bp[(ks * 16 + wn * 4 + nt) * 32 + lane];
#pragma unroll
            for (int mt = 0; mt < 4; mt++) {
                float* c = acc[mt][nt];
                MMA_BF16(c, ahi[mt], b.x, b.y);   // hi*hi
                MMA_BF16(c, ahi[mt], b.z, b.w);   // hi*lo
                MMA_BF16(c, alo[mt], b.x, b.y);   // lo*hi
            }
        }
    }
}

// relu(acc + bias) -> split -> z smem buffers (C-frag pair (c0,c1) is an adjacent k-pair)
__device__ __forceinline__ void store_z(float (*acc)[4][4], const float* __restrict__ bias,
                                        unsigned* zhi, unsigned* zlo) {
    int tid = threadIdx.x;
    int wid = tid >> 5, lane = tid & 31;
    int wm = wid >> 2, wn = wid & 3;
    int m0 = wm * 64, n0 = wn * 32;
    int tig = lane & 3, grp = lane >> 2;
#pragma unroll
    for (int nt = 0; nt < 4; nt++) {
        int col = n0 + nt * 8 + 2 * tig;
        float b0 = bias[col], b1 = bias[col + 1];
        int pc = col >> 1;
#pragma unroll
        for (int mt = 0; mt < 4; mt++) {
            int r = m0 + mt * 16 + grp;
            float* c = acc[mt][nt];
            float u0 = fmaxf(c[0] + b0, 0.f), u1 = fmaxf(c[1] + b1, 0.f);
            float u2 = fmaxf(c[2] + b0, 0.f), u3 = fmaxf(c[3] + b1, 0.f);
            unsigned h, l;
            bf16_split_pair(u0, u1, h, l);
            zhi[r * FSTR + pc] = h; zlo[r * FSTR + pc] = l;
            bf16_split_pair(u2, u3, h, l);
            zhi[(r + 8) * FSTR + pc] = h; zlo[(r + 8) * FSTR + pc] = l;
        }
    }
}

__device__ __forceinline__ void gemm_epilogue_y(float (*acc)[4][4],
                                                float* __restrict__ C, int ldc, int row0) {
    int tid = threadIdx.x;
    int wid = tid >> 5, lane = tid & 31;
    int wm = wid >> 2, wn = wid & 3;
    int m0 = wm * 64, n0 = wn * 32;
    int tig = lane & 3, grp = lane >> 2;
#pragma unroll
    for (int nt = 0; nt < 4; nt++) {
        int col = n0 + nt * 8 + 2 * tig;
#pragma unroll
        for (int mt = 0; mt < 4; mt++) {
            int r = row0 + m0 + mt * 16 + grp;
            float* c = acc[mt][nt];
            if (r < NNODES)
                *(float2*)&C[(size_t)r * ldc + col] = make_float2(c[0], c[1]);
            int r2 = r + 8;
            if (r2 < NNODES)
                *(float2*)&C[(size_t)r2 * ldc + col] = make_float2(c[2], c[3]);
        }
    }
}

// fused 2-layer GEMM per (gate, row-tile): z never leaves the SM.
__global__ __launch_bounds__(256) void k_mma_fused(const float* __restrict__ bx0,
                                                   const float* __restrict__ bh0) {
    extern __shared__ unsigned sm[];
    unsigned *Ah  = sm,            *Al  = sm + ZOFF;
    unsigned *zxh = sm + 2 * ZOFF, *zxl = sm + 3 * ZOFF;
    unsigned *zhh = sm + 4 * ZOFF, *zhl = sm + 5 * ZOFF;
    int g = blockIdx.y;
    int row0 = blockIdx.x * 128;

    {   // layer-1 x-branch: z_x = relu(ax @ Wx0[g] + bx0[g])
        float accz[4][4][4];
#pragma unroll
        for (int a = 0; a < 4; a++)
#pragma unroll
            for (int b = 0; b < 4; b++)
#pragma unroll
                for (int cc = 0; cc < 4; cc++) accz[a][b][cc] = 0.f;
        stage_split(g_ax, 128, row0, Ah, Al);
        __syncthreads();
        mma_pass(accz, Ah, Al, g);
        store_z(accz, bx0 + g * 128, zxh, zxl);
    }
    __syncthreads();    // A consumed by all warps before restaging
    {   // layer-1 h-branch: z_h = relu(ah @ Wh0[g] + bh0[g])
        float accz[4][4][4];
#pragma unroll
        for (int a = 0; a < 4; a++)
#pragma unroll
            for (int b = 0; b < 4; b++)
#pragma unroll
                for (int cc = 0; cc < 4; cc++) accz[a][b][cc] = 0.f;
        stage_split(g_ah, 128, row0, Ah, Al);
        __syncthreads();
        mma_pass(accz, Ah, Al, 4 + g);
        store_z(accz, bh0 + g * 128, zhh, zhl);
    }
    __syncthreads();    // z buffers complete
    // layer-2: y = z_x @ Wx1[g] + z_h @ Wh1[g]   (bias deferred to LSTM)
    float accy[4][4][4];
#pragma unroll
    for (int a = 0; a < 4; a++)
#pragma unroll
        for (int b = 0; b < 4; b++)
#pragma unroll
            for (int cc = 0; cc < 4; cc++) accy[a][b][cc] = 0.f;
    mma_pass(accy, zxh, zxl, 8 + g);
    mma_pass(accy, zhh, zhl, 12 + g);
    gemm_epilogue_y(accy, g_y + g * 128, 512, row0);
}

// ---------------- fused F=512 gather + LSTM epilogue: one block (128 thr) per node ----------------
__device__ __forceinline__ float sigmoidf_(float v) { return 1.f / (1.f + expf(-v)); }

__global__ void __launch_bounds__(128) k_gather_lstm(
    const float* __restrict__ c,
    const float* __restrict__ bx1, const float* __restrict__ bh1,
    const float* __restrict__ wc, const float* __restrict__ bg,
    float* __restrict__ out)
{
    __shared__ float sG[512];
    int n = blockIdx.x;
    int t = threadIdx.x;
    float sd = g_dis[n];
    float s2 = sd * sd;
    float4 v = ((const float4*)(g_y + (size_t)n * 512))[t];
    float4 acc = make_float4(s2 * v.x, s2 * v.y, s2 * v.z, s2 * v.w);
    int e0 = g_rowptr[n], e1 = g_rowptr[n + 1];
#pragma unroll 4
    for (int e = e0; e < e1; ++e) {
        int cc = g_ecol[e];
        float nm = g_enorm[e];
        float4 yv = ((const float4*)(g_y + (size_t)cc * 512))[t];
        acc.x = fmaf(nm, yv.x, acc.x); acc.y = fmaf(nm, yv.y, acc.y);
        acc.z = fmaf(nm, yv.z, acc.z); acc.w = fmaf(nm, yv.w, acc.w);
    }
    ((float4*)sG)[t] = acc;
    __syncthreads();
    int f = t;
    int idx = n * HD + f;
    float cv = c[idx];
    float Gi = sG[f]       + bx1[f]       + bh1[f];
    float Gf = sG[128 + f] + bx1[128 + f] + bh1[128 + f];
    float Gc = sG[256 + f] + bx1[256 + f] + bh1[256 + f];
    float Go = sG[384 + f] + bx1[384 + f] + bh1[384 + f];
    float I  = sigmoidf_(Gi + wc[f] * cv + bg[f]);
    float Fg = sigmoidf_(Gf + wc[128 + f] * cv + bg[128 + f]);
    float T  = tanhf(Gc + bg[256 + f]);
    float Cn = Fg * cv + I * T;
    float O  = sigmoidf_(Go + wc[256 + f] * Cn + bg[384 + f]);
    float Hn = O * tanhf(Cn);
    out[idx] = Hn;
    out[(size_t)NNODES * HD + idx] = Cn;
}

// ---------------- launch ----------------
extern "C" void kernel_launch(void* const* d_in, const int* in_sizes, int n_in,
                              void* d_out, int out_size) {
    const float* x   = (const float*)d_in[0];
    const void*  ei  = d_in[1];                 // int32 or int64, detected on device
    const float* w   = (const float*)d_in[2];
    const float* h   = (const float*)d_in[3];
    const float* c   = (const float*)d_in[4];
    const float* Wx0 = (const float*)d_in[5];
    const float* bx0 = (const float*)d_in[6];
    const float* Wx1 = (const float*)d_in[7];
    const float* bx1 = (const float*)d_in[8];
    const float* Wh0 = (const float*)d_in[9];
    const float* bh0 = (const float*)d_in[10];
    const float* Wh1 = (const float*)d_in[11];
    const float* bh1 = (const float*)d_in[12];
    const float* wc  = (const float*)d_in[13];
    const float* bg  = (const float*)d_in[14];
    float* out = (float*)d_out;

    static int smem_set = 0;
    if (!smem_set) {
        cudaFuncSetAttribute(k_mma_fused, cudaFuncAttributeMaxDynamicSharedMemorySize,
                             SMEM_FUSED_BYTES);
        smem_set = 1;
    }

    const int T = 256;
    // prologue
    k_init<<<(NNODES + T - 1) / T, T>>>((const int*)ei);
    k_wprep<<<(16 * 8 * 16 * 32 + T - 1) / T, T>>>(Wx0, Wh0, Wx1, Wh1);
    k_edge_prep<<<(NEDGES + T - 1) / T, T>>>(ei, w);
    k_scan1<<<NSB, 1024>>>();
    k_scan2<<<NSB, 1024>>>();
    k_scatter<<<(NEDGES + T - 1) / T, T>>>(ei, w);

    // fused first props (F=128) for x and h, gather-based
    k_gather_xh<<<(NNODES * 32 + T - 1) / T, T>>>(x, h);

    // fused 2-layer tensor-core GEMM (z stays on-chip)
    dim3 gm((NNODES + 127) / 128, 4);
    k_mma_fused<<<gm, 256, SMEM_FUSED_BYTES>>>(bx0, bh0);

    // fused F=512 gather + LSTM epilogue
    k_gather_lstm<<<NNODES, 128>>>(c, bx1, bh1, wc, bg, out);
}

// round 10
// speedup vs baseline: 5.1488x; 1.0539x over previous
#include <cuda_runtime.h>
#include <math.h>

#define NNODES 20000
#define NEDGES 320000
#define HD 128
#define FSTR 68                  // pair-column stride (words), conflict-free
#define ZOFF (128 * FSTR)        // words per hi/lo array
#define SMEM_FUSED_BYTES (6 * ZOFF * 4)   // As + zx + zh, hi+lo each = 208896 B
#define NPB 1000                 // nodes per scan block
#define NSB 20                   // scan blocks

// ---------------- scratch (static device allocations) ----------------
__device__ int   g_is64;
__device__ __align__(16) float g_deg[NNODES];
__device__ __align__(16) int   g_cnt[NNODES];
__device__ __align__(16) int   g_bsum[NSB];
__device__ __align__(16) int   g_rowptr[NNODES + 4];
__device__ __align__(16) int   g_cur[NNODES + 4];
__device__ __align__(16) float g_dis[NNODES];
__device__ __align__(16) int   g_ecol[NEDGES];    // CSR (by dst): src node
__device__ __align__(16) float g_enorm[NEDGES];   // CSR (by dst): edge norm
__device__ __align__(16) float g_ax[(size_t)NNODES * HD];   // prop(x)
__device__ __align__(16) float g_ah[(size_t)NNODES * HD];   // prop(h)
__device__ __align__(16) float g_y[(size_t)NNODES * 512];   // pre-prop gate features
// pre-split bf16 weights: [stream 16][ks 8][nt 16][lane 32] = (hi0,hi1,lo0,lo1)
__device__ __align__(16) uint4 g_Bp[16 * 8 * 16 * 32];

// bf16 truncation split of a k-pair (x0=even k, x1=odd k) into packed bf16x2 regs.
__device__ __forceinline__ void bf16_split_pair(float x0, float x1,
                                                unsigned &hi, unsigned &lo) {
    unsigned b0 = __float_as_uint(x0), b1 = __float_as_uint(x1);
    hi = __byte_perm(b0, b1, 0x7632);              // {lo16=top16(x0), hi16=top16(x1)}
    float l0 = x0 - __uint_as_float(b0 & 0xFFFF0000u);
    float l1 = x1 - __uint_as_float(b1 & 0xFFFF0000u);
    asm("cvt.rn.bf16x2.f32 %0, %1, %2;" : "=r"(lo) : "f"(l1), "f"(l0));
}

// ---------------- init deg/cnt + edge dtype detect (block 0) ----------------
__global__ void k_init(const int* __restrict__ ei32) {
    int i = blockIdx.x * blockDim.x + threadIdx.x;
    if (i < NNODES) { g_deg[i] = 1.0f; g_cnt[i] = 0; }   // self-loop weight 1
    if (blockIdx.x == 0) {
        __shared__ int nz;
        if (threadIdx.x == 0) nz = 0;
        __syncthreads();
        if (threadIdx.x < 128) {
            if (ei32[2 * threadIdx.x + 1] != 0) atomicAdd(&nz, 1);
        }
        __syncthreads();
        if (threadIdx.x == 0) g_is64 = (nz == 0) ? 1 : 0;
    }
}

// ---------------- 4-edge decode ----------------
__device__ __forceinline__ void edge_decode4(const void* __restrict__ ei_raw, int e4,
                                             int* s, int* d) {
    if (g_is64) {
        const long long* ei = (const long long*)ei_raw;
        longlong2 s01 = *(const longlong2*)(ei + e4);
        longlong2 s23 = *(const longlong2*)(ei + e4 + 2);
        longlong2 d01 = *(const longlong2*)(ei + NEDGES + e4);
        longlong2 d23 = *(const longlong2*)(ei + NEDGES + e4 + 2);
        s[0] = (int)s01.x; s[1] = (int)s01.y; s[2] = (int)s23.x; s[3] = (int)s23.y;
        d[0] = (int)d01.x; d[1] = (int)d01.y; d[2] = (int)d23.x; d[3] = (int)d23.y;
    } else {
        const int* ei = (const int*)ei_raw;
        int4 sv = *(const int4*)(ei + e4);
        int4 dv = *(const int4*)(ei + NEDGES + e4);
        s[0] = sv.x; s[1] = sv.y; s[2] = sv.z; s[3] = sv.w;
        d[0] = dv.x; d[1] = dv.y; d[2] = dv.z; d[3] = dv.w;
    }
#pragma unroll
    for (int i = 0; i < 4; i++) {
        if ((unsigned)s[i] >= NNODES) s[i] = 0;
        if ((unsigned)d[i] >= NNODES) d[i] = 0;
    }
}

// ---------------- edge histograms (4 edges / thread) ----------------
__global__ void k_edge_prep(const void* __restrict__ ei_raw,
                            const float* __restrict__ w) {
    int e4 = (blockIdx.x * blockDim.x + threadIdx.x) * 4;
    if (e4 >= NEDGES) return;
    int s[4], d[4];
    edge_decode4(ei_raw, e4, s, d);
    float4 wv = *(const float4*)(w + e4);
    atomicAdd(&g_deg[d[0]], wv.x); atomicAdd(&g_cnt[d[0]], 1);
    atomicAdd(&g_deg[d[1]], wv.y); atomicAdd(&g_cnt[d[1]], 1);
    atomicAdd(&g_deg[d[2]], wv.z); atomicAdd(&g_cnt[d[2]], 1);
    atomicAdd(&g_deg[d[3]], wv.w); atomicAdd(&g_cnt[d[3]], 1);
}

// ---------------- parallel scan phase 1: block sums + dis ----------------
__global__ void k_scan1() {          // grid NSB x 1024
    int b = blockIdx.x, t = threadIdx.x;
    int base = b * NPB;
    int v = (t < NPB) ? g_cnt[base + t] : 0;
    int s = v;
#pragma unroll
    for (int off = 16; off > 0; off >>= 1) s += __shfl_down_sync(0xFFFFFFFFu, s, off);
    __shared__ int wsum[32];
    int lane = t & 31, wid = t >> 5;
    if (lane == 0) wsum[wid] = s;
    __syncthreads();
    if (wid == 0) {
        int x = wsum[lane];
#pragma unroll
        for (int off = 16; off > 0; off >>= 1) x += __shfl_down_sync(0xFFFFFFFFu, x, off);
        if (lane == 0) g_bsum[b] = x;
    }
    if (t < NPB) {
        float dg = g_deg[base + t];
        g_dis[base + t] = dg > 0.f ? rsqrtf(fmaxf(dg, 1e-12f)) : 0.f;
    }
}

// ---------------- parallel scan phase 2: write rowptr/cur ----------------
__global__ void k_scan2() {          // grid NSB x 1024
    int b = blockIdx.x, t = threadIdx.x;
    int lane = t & 31, wid = t >> 5;
    __shared__ int sbase;
    __shared__ int wsum[32];
    if (wid == 0) {
        int x = (lane < b) ? g_bsum[lane] : 0;
#pragma unroll
        for (int off = 16; off > 0; off >>= 1) x += __shfl_down_sync(0xFFFFFFFFu, x, off);
        if (lane == 0) sbase = x;
    }
    int base = b * NPB;
    int v = (t < NPB) ? g_cnt[base + t] : 0;
    int incl = v;
#pragma unroll
    for (int off = 1; off < 32; off <<= 1) {
        int n = __shfl_up_sync(0xFFFFFFFFu, incl, off);
        if (lane >= off) incl += n;
    }
    if (lane == 31) wsum[wid] = incl;
    __syncthreads();
    if (wid == 0) {
        int wv = wsum[lane];
        int wi = wv;
#pragma unroll
        for (int off = 1; off < 32; off <<= 1) {
            int n = __shfl_up_sync(0xFFFFFFFFu, wi, off);
            if (lane >= off) wi += n;
        }
        wsum[lane] = wi - wv;   // exclusive warp base
    }
    __syncthreads();
    if (t < NPB) {
        int excl = sbase + wsum[wid] + incl - v;
        g_rowptr[base + t] = excl;
        g_cur[base + t] = excl;
    }
    if (b == NSB - 1 && t == 0) g_rowptr[NNODES] = NEDGES;
}

// ---------------- scatter edges into CSR + compute norm (4 edges / thread) ----------------
__global__ void k_scatter(const void* __restrict__ ei_raw, const float* __restrict__ w) {
    int e4 = (blockIdx.x * blockDim.x + threadIdx.x) * 4;
    if (e4 >= NEDGES) return;
    int s[4], d[4];
    edge_decode4(ei_raw, e4, s, d);
    float4 wv = *(const float4*)(w + e4);
    float wa[4] = {wv.x, wv.y, wv.z, wv.w};
#pragma unroll
    for (int i = 0; i < 4; i++) {
        int pos = atomicAdd(&g_cur[d[i]], 1);
        g_ecol[pos] = s[i];
        g_enorm[pos] = g_dis[s[i]] * wa[i] * g_dis[d[i]];
    }
}

// ---------------- weight prep: bf16 hi/lo split, B-fragment order (m16n8k16) ----------------
// streams: 0-3 Wx0[g], 4-7 Wh0[g], 8-11 Wx1[g], 12-15 Wh1[g]
__global__ void k_wprep(const float* __restrict__ Wx0, const float* __restrict__ Wh0,
                        const float* __restrict__ Wx1, const float* __restrict__ Wh1) {
    int idx = blockIdx.x * blockDim.x + threadIdx.x;    // 16*8*16*32 = 65536
    if (idx >= 16 * 8 * 16 * 32) return;
    int s    = idx >> 12;          // stream
    int ks   = (idx >> 9) & 7;     // k-step (k0 = ks*16)
    int nt   = (idx >> 5) & 15;    // n-tile (n0 = nt*8)
    int lane = idx & 31;
    const float* W;
    if (s < 4)       W = Wx0 + s * 16384;
    else if (s < 8)  W = Wh0 + (s - 4) * 16384;
    else if (s < 12) W = Wx1 + (s - 8) * 16384;
    else             W = Wh1 + (s - 12) * 16384;
    int tig = lane & 3, grp = lane >> 2;
    int k0 = ks * 16, n = nt * 8 + grp;
    float w0 = W[(k0 + 2 * tig)     * 128 + n];
    float w1 = W[(k0 + 2 * tig + 1) * 128 + n];
    float w2 = W[(k0 + 2 * tig + 8) * 128 + n];
    float w3 = W[(k0 + 2 * tig + 9) * 128 + n];
    unsigned h0, l0, h1, l1;
    bf16_split_pair(w0, w1, h0, l0);
    bf16_split_pair(w2, w3, h1, l1);
    g_Bp[idx] = make_uint4(h0, h1, l0, l1);
}

// ---------------- fused gather SpMM for x and h (F=128), one warp per node ----------------
__global__ void k_gather_xh(const float* __restrict__ x, const float* __restrict__ h) {
    int warp = (blockIdx.x * blockDim.x + threadIdx.x) >> 5;
    int lane = threadIdx.x & 31;
    if (warp >= NNODES) return;
    int n = warp;
    float sd = g_dis[n];
    float s2 = sd * sd;
    float4 xv = *((const float4*)(x + (size_t)n * HD) + lane);
    float4 hv = *((const float4*)(h + (size_t)n * HD) + lane);
    float4 ax = make_float4(s2 * xv.x, s2 * xv.y, s2 * xv.z, s2 * xv.w);
    float4 ah = make_float4(s2 * hv.x, s2 * hv.y, s2 * hv.z, s2 * hv.w);
    int e0 = g_rowptr[n], e1 = g_rowptr[n + 1];
#pragma unroll 4
    for (int e = e0; e < e1; ++e) {
        int c = g_ecol[e];
        float nm = g_enorm[e];
        float4 cx = *((const float4*)(x + (size_t)c * HD) + lane);
        float4 ch = *((const float4*)(h + (size_t)c * HD) + lane);
        ax.x = fmaf(nm, cx.x, ax.x); ax.y = fmaf(nm, cx.y, ax.y);
        ax.z = fmaf(nm, cx.z, ax.z); ax.w = fmaf(nm, cx.w, ax.w);
        ah.x = fmaf(nm, ch.x, ah.x); ah.y = fmaf(nm, ch.y, ah.y);
        ah.z = fmaf(nm, ch.z, ah.z); ah.w = fmaf(nm, ch.w, ah.w);
    }
    ((float4*)(g_ax + (size_t)n * HD))[lane] = ax;
    ((float4*)(g_ah + (size_t)n * HD))[lane] = ah;
}

// ---------------- tensor-core GEMM building blocks (m16n8k16 bf16, 3-term split) ----------------
#define MMA_BF16(c, a, bb0, bb1) \
    asm("mma.sync.aligned.m16n8k16.row.col.f32.bf16.bf16.f32 " \
        "{%0,%1,%2,%3},{%4,%5,%6,%7},{%8,%9},{%0,%1,%2,%3};" \
        : "+f"(c[0]), "+f"(c[1]), "+f"(c[2]), "+f"(c[3]) \
        : "r"(a[0]), "r"(a[1]), "r"(a[2]), "r"(a[3]), "r"(bb0), "r"(bb1))

// volatile + memory clobber: the load must NOT be reordered across __syncthreads()
// or the shared-memory staging stores (Ah/Al are re-staged between passes).
#define LDSM_X4(r, addr) \
    asm volatile("ldmatrix.sync.aligned.m8n8.x4.shared.b16 {%0,%1,%2,%3}, [%4];" \
        : "=r"(r[0]), "=r"(r[1]), "=r"(r[2]), "=r"(r[3]) : "r"(addr) : "memory")

// stage a 128x128 fp32 tile from global, split into hi/lo bf16x2-pair smem arrays
__device__ __forceinline__ void stage_split(const float* __restrict__ A, int lda, int row0,
                                            unsigned* hi_arr, unsigned* lo_arr) {
    int tid = threadIdx.x;
    float4 v[16];
#pragma unroll
    for (int i = 0; i < 16; i++) {
        int f = i * 256 + tid;            // 0..4095
        int row = f >> 5;                 // 0..127
        int c4 = (f & 31) * 4;            // 0..124
        int grow = row0 + row;
        v[i] = (grow < NNODES) ? *(const float4*)(A + (size_t)grow * lda + c4)
                               : make_float4(0.f, 0.f, 0.f, 0.f);
    }
#pragma unroll
    for (int i = 0; i < 16; i++) {
        int f = i * 256 + tid;
        int row = f >> 5;
        int pc = (f & 31) * 2;            // pair column (even)
        unsigned h0, l0, h1, l1;
        bf16_split_pair(v[i].x, v[i].y, h0, l0);
        bf16_split_pair(v[i].z, v[i].w, h1, l1);
        hi_arr[row * FSTR + pc] = h0; hi_arr[row * FSTR + pc + 1] = h1;
        lo_arr[row * FSTR + pc] = l0; lo_arr[row * FSTR + pc + 1] = l1;
    }
}

// acc += (smem A tile) @ (pre-split B stream), 3-term split; A frags via ldmatrix
__device__ __forceinline__ void mma_pass(float (*acc)[4][4],
                                         const unsigned* As_hi, const unsigned* As_lo,
                                         int stream) {
    int tid = threadIdx.x;
    int wid = tid >> 5, lane = tid & 31;
    int wm = wid >> 2, wn = wid & 3;
    int m0 = wm * 64;
    const uint4* __restrict__ Bp = g_Bp + (stream << 12);
    // ldmatrix lane->address map: lanes 0-7: rows 0-7 (k-low); 8-15: rows 8-15 (k-low);
    // 16-23: rows 0-7 (k-high); 24-31: rows 8-15 (k-high)
    int lrow = (lane & 7) + ((lane >> 3) & 1) * 8;
    int lcol = (lane >> 4) * 4;
    unsigned hi_base = (unsigned)__cvta_generic_to_shared(As_hi)
                     + ((m0 + lrow) * FSTR + lcol) * 4;
    unsigned lo_base = (unsigned)__cvta_generic_to_shared(As_lo)
                     + ((m0 + lrow) * FSTR + lcol) * 4;
#pragma unroll
    for (int ks = 0; ks < 8; ks++) {
        unsigned ahi[4][4], alo[4][4];
#pragma unroll
        for (int mt = 0; mt < 4; mt++) {
            unsigned off = (mt * 16 * FSTR + ks * 8) * 4;
            LDSM_X4(ahi[mt], hi_base + off);
            LDSM_X4(alo[mt], lo_base + off);
        }
#pragma unroll
        for (int nt = 0; nt < 4; nt++) {
            uint4 b = Bp[(ks * 16 + wn * 4 + nt) * 32 + lane];
#pragma unroll
            for (int mt = 0; mt < 4; mt++) {
                float* c = acc[mt][nt];
                MMA_BF16(c, ahi[mt], b.x, b.y);   // hi*hi
                MMA_BF16(c, ahi[mt], b.z, b.w);   // hi*lo
                MMA_BF16(c, alo[mt], b.x, b.y);   // lo*hi
            }
        }
    }
}

// relu(acc + bias) -> split -> z smem buffers (C-frag pair (c0,c1) is an adjacent k-pair)
__device__ __forceinline__ void store_z(float (*acc)[4][4], const float* __restrict__ bias,
                                        unsigned* zhi, unsigned* zlo) {
    int tid = threadIdx.x;
    int wid = tid >> 5, lane = tid & 31;
    int wm = wid >> 2, wn = wid & 3;
    int m0 = wm * 64, n0 = wn * 32;
    int tig = lane & 3, grp = lane >> 2;
#pragma unroll
    for (int nt = 0; nt < 4; nt++) {
        int col = n0 + nt * 8 + 2 * tig;
        float b0 = bias[col], b1 = bias[col + 1];
        int pc = col >> 1;
#pragma unroll
        for (int mt = 0; mt < 4; mt++) {
            int r = m0 + mt * 16 + grp;
            float* c = acc[mt][nt];
            float u0 = fmaxf(c[0] + b0, 0.f), u1 = fmaxf(c[1] + b1, 0.f);
            float u2 = fmaxf(c[2] + b0, 0.f), u3 = fmaxf(c[3] + b1, 0.f);
            unsigned h, l;
            bf16_split_pair(u0, u1, h, l);
            zhi[r * FSTR + pc] = h; zlo[r * FSTR + pc] = l;
            bf16_split_pair(u2, u3, h, l);
            zhi[(r + 8) * FSTR + pc] = h; zlo[(r + 8) * FSTR + pc] = l;
        }
    }
}

__device__ __forceinline__ void gemm_epilogue_y(float (*acc)[4][4],
                                                float* __restrict__ C, int ldc, int row0) {
    int tid = threadIdx.x;
    int wid = tid >> 5, lane = tid & 31;
    int wm = wid >> 2, wn = wid & 3;
    int m0 = wm * 64, n0 = wn * 32;
    int tig = lane & 3, grp = lane >> 2;
#pragma unroll
    for (int nt = 0; nt < 4; nt++) {
        int col = n0 + nt * 8 + 2 * tig;
#pragma unroll
        for (int mt = 0; mt < 4; mt++) {
            int r = row0 + m0 + mt * 16 + grp;
            float* c = acc[mt][nt];
            if (r < NNODES)
                *(float2*)&C[(size_t)r * ldc + col] = make_float2(c[0], c[1]);
            int r2 = r + 8;
            if (r2 < NNODES)
                *(float2*)&C[(size_t)r2 * ldc + col] = make_float2(c[2], c[3]);
        }
    }
}

// fused 2-layer GEMM per (gate, row-tile): z never leaves the SM.
__global__ __launch_bounds__(256) void k_mma_fused(const float* __restrict__ bx0,
                                                   const float* __restrict__ bh0) {
    extern __shared__ unsigned sm[];
    unsigned *Ah  = sm,            *Al  = sm + ZOFF;
    unsigned *zxh = sm + 2 * ZOFF, *zxl = sm + 3 * ZOFF;
    unsigned *zhh = sm + 4 * ZOFF, *zhl = sm + 5 * ZOFF;
    int g = blockIdx.y;
    int row0 = blockIdx.x * 128;

    {   // layer-1 x-branch: z_x = relu(ax @ Wx0[g] + bx0[g])
        float accz[4][4][4];
#pragma unroll
        for (int a = 0; a < 4; a++)
#pragma unroll
            for (int b = 0; b < 4; b++)
#pragma unroll
                for (int cc = 0; cc < 4; cc++) accz[a][b][cc] = 0.f;
        stage_split(g_ax, 128, row0, Ah, Al);
        __syncthreads();
        mma_pass(accz, Ah, Al, g);
        store_z(accz, bx0 + g * 128, zxh, zxl);
    }
    __syncthreads();    // A consumed by all warps before restaging
    {   // layer-1 h-branch: z_h = relu(ah @ Wh0[g] + bh0[g])
        float accz[4][4][4];
#pragma unroll
        for (int a = 0; a < 4; a++)
#pragma unroll
            for (int b = 0; b < 4; b++)
#pragma unroll
                for (int cc = 0; cc < 4; cc++) accz[a][b][cc] = 0.f;
        stage_split(g_ah, 128, row0, Ah, Al);
        __syncthreads();
        mma_pass(accz, Ah, Al, 4 + g);
        store_z(accz, bh0 + g * 128, zhh, zhl);
    }
    __syncthreads();    // z buffers complete
    // layer-2: y = z_x @ Wx1[g] + z_h @ Wh1[g]   (bias deferred to LSTM)
    float accy[4][4][4];
#pragma unroll
    for (int a = 0; a < 4; a++)
#pragma unroll
        for (int b = 0; b < 4; b++)
#pragma unroll
            for (int cc = 0; cc < 4; cc++) accy[a][b][cc] = 0.f;
    mma_pass(accy, zxh, zxl, 8 + g);
    mma_pass(accy, zhh, zhl, 12 + g);
    gemm_epilogue_y(accy, g_y + g * 128, 512, row0);
}

// ---------------- fused F=512 gather + LSTM epilogue: one block (128 thr) per node ----------------
__device__ __forceinline__ float sigmoidf_(float v) { return 1.f / (1.f + expf(-v)); }

__global__ void __launch_bounds__(128) k_gather_lstm(
    const float* __restrict__ c,
    const float* __restrict__ bx1, const float* __restrict__ bh1,
    const float* __restrict__ wc, const float* __restrict__ bg,
    float* __restrict__ out)
{
    __shared__ float sG[512];
    int n = blockIdx.x;
    int t = threadIdx.x;
    float sd = g_dis[n];
    float s2 = sd * sd;
    float4 v = ((const float4*)(g_y + (size_t)n * 512))[t];
    float4 acc = make_float4(s2 * v.x, s2 * v.y, s2 * v.z, s2 * v.w);
    int e0 = g_rowptr[n], e1 = g_rowptr[n + 1];
#pragma unroll 4
    for (int e = e0; e < e1; ++e) {
        int cc = g_ecol[e];
        float nm = g_enorm[e];
        float4 yv = ((const float4*)(g_y + (size_t)cc * 512))[t];
        acc.x = fmaf(nm, yv.x, acc.x); acc.y = fmaf(nm, yv.y, acc.y);
        acc.z = fmaf(nm, yv.z, acc.z); acc.w = fmaf(nm, yv.w, acc.w);
    }
    ((float4*)sG)[t] = acc;
    __syncthreads();
    int f = t;
    int idx = n * HD + f;
    float cv = c[idx];
    float Gi = sG[f]       + bx1[f]       + bh1[f];
    float Gf = sG[128 + f] + bx1[128 + f] + bh1[128 + f];
    float Gc = sG[256 + f] + bx1[256 + f] + bh1[256 + f];
    float Go = sG[384 + f] + bx1[384 + f] + bh1[384 + f];
    float I  = sigmoidf_(Gi + wc[f] * cv + bg[f]);
    float Fg = sigmoidf_(Gf + wc[128 + f] * cv + bg[128 + f]);
    float T  = tanhf(Gc + bg[256 + f]);
    float Cn = Fg * cv + I * T;
    float O  = sigmoidf_(Go + wc[256 + f] * Cn + bg[384 + f]);
    float Hn = O * tanhf(Cn);
    out[idx] = Hn;
    out[(size_t)NNODES * HD + idx] = Cn;
}

// ---------------- launch ----------------
extern "C" void kernel_launch(void* const* d_in, const int* in_sizes, int n_in,
                              void* d_out, int out_size) {
    const float* x   = (const float*)d_in[0];
    const void*  ei  = d_in[1];                 // int32 or int64, detected on device
    const float* w   = (const float*)d_in[2];
    const float* h   = (const float*)d_in[3];
    const float* c   = (const float*)d_in[4];
    const float* Wx0 = (const float*)d_in[5];
    const float* bx0 = (const float*)d_in[6];
    const float* Wx1 = (const float*)d_in[7];
    const float* bx1 = (const float*)d_in[8];
    const float* Wh0 = (const float*)d_in[9];
    const float* bh0 = (const float*)d_in[10];
    const float* Wh1 = (const float*)d_in[11];
    const float* bh1 = (const float*)d_in[12];
    const float* wc  = (const float*)d_in[13];
    const float* bg  = (const float*)d_in[14];
    float* out = (float*)d_out;

    static int smem_set = 0;
    if (!smem_set) {
        cudaFuncSetAttribute(k_mma_fused, cudaFuncAttributeMaxDynamicSharedMemorySize,
                             SMEM_FUSED_BYTES);
        smem_set = 1;
    }

    const int T = 256;
    // prologue
    k_init<<<(NNODES + T - 1) / T, T>>>((const int*)ei);
    k_edge_prep<<<(NEDGES / 4 + T - 1) / T, T>>>(ei, w);
    k_scan1<<<NSB, 1024>>>();
    k_scan2<<<NSB, 1024>>>();
    k_scatter<<<(NEDGES / 4 + T - 1) / T, T>>>(ei, w);

    // fused first props (F=128) for x and h, gather-based
    k_gather_xh<<<(NNODES * 32 + T - 1) / T, T>>>(x, h);

    // weight prep (independent of everything above except weights)
    k_wprep<<<(16 * 8 * 16 * 32 + T - 1) / T, T>>>(Wx0, Wh0, Wx1, Wh1);

    // fused 2-layer tensor-core GEMM (z stays on-chip)
    dim3 gm((NNODES + 127) / 128, 4);
    k_mma_fused<<<gm, 256, SMEM_FUSED_BYTES>>>(bx0, bh0);

    // fused F=512 gather + LSTM epilogue
    k_gather_lstm<<<NNODES, 128>>>(c, bx1, bh1, wc, bg, out);
}

// round 11
// speedup vs baseline: 5.2976x; 1.0289x over previous
#include <cuda_runtime.h>
#include <math.h>

#define NNODES 20000
#define NEDGES 320000
#define HD 128
#define FSTR 68                  // pair-column stride (words), conflict-free
#define ZOFF (128 * FSTR)        // words per hi/lo array
#define SMEM_FUSED_BYTES (6 * ZOFF * 4)   // As + zx + zh, hi+lo each = 208896 B
#define NPB 1000                 // nodes per scan block
#define NSB 20                   // scan blocks

// ---------------- scratch (static device allocations) ----------------
__device__ int   g_is64;
__device__ __align__(16) float g_deg[NNODES];
__device__ __align__(16) int   g_cnt[NNODES];
__device__ volatile int g_bsum_v[NSB];
__device__ volatile int g_bflag[NSB];
__device__ __align__(16) int   g_rowptr[NNODES + 4];
__device__ __align__(16) int   g_cur[NNODES + 4];
__device__ __align__(16) float g_dis[NNODES];
__device__ __align__(16) int   g_ecol[NEDGES];    // CSR (by dst): src node
__device__ __align__(16) float g_enorm[NEDGES];   // CSR (by dst): edge norm
__device__ __align__(16) float g_ax[(size_t)NNODES * HD];   // prop(x)
__device__ __align__(16) float g_ah[(size_t)NNODES * HD];   // prop(h)
__device__ __align__(16) float g_y[(size_t)NNODES * 512];   // pre-prop gate features
// pre-split bf16 weights: [stream 16][ks 8][nt 16][lane 32] = (hi0,hi1,lo0,lo1)
__device__ __align__(16) uint4 g_Bp[16 * 8 * 16 * 32];

// bf16 truncation split of a k-pair (x0=even k, x1=odd k) into packed bf16x2 regs.
__device__ __forceinline__ void bf16_split_pair(float x0, float x1,
                                                unsigned &hi, unsigned &lo) {
    unsigned b0 = __float_as_uint(x0), b1 = __float_as_uint(x1);
    hi = __byte_perm(b0, b1, 0x7632);              // {lo16=top16(x0), hi16=top16(x1)}
    float l0 = x0 - __uint_as_float(b0 & 0xFFFF0000u);
    float l1 = x1 - __uint_as_float(b1 & 0xFFFF0000u);
    asm("cvt.rn.bf16x2.f32 %0, %1, %2;" : "=r"(lo) : "f"(l1), "f"(l0));
}

// ---------------- merged init (deg/cnt/flags + dtype detect) + weight prep ----------------
// blocks 0..255: wprep; blocks 256..334: init; block 256 also runs dtype detect.
__global__ void k_init_wprep(const int* __restrict__ ei32,
                             const float* __restrict__ Wx0, const float* __restrict__ Wh0,
                             const float* __restrict__ Wx1, const float* __restrict__ Wh1) {
    int b = blockIdx.x, t = threadIdx.x;
    if (b < 256) {
        int idx = b * 256 + t;            // 0..65535
        int s    = idx >> 12;             // stream
        int ks   = (idx >> 9) & 7;        // k-step (k0 = ks*16)
        int nt   = (idx >> 5) & 15;       // n-tile (n0 = nt*8)
        int lane = idx & 31;
        const float* W;
        if (s < 4)       W = Wx0 + s * 16384;
        else if (s < 8)  W = Wh0 + (s - 4) * 16384;
        else if (s < 12) W = Wx1 + (s - 8) * 16384;
        else             W = Wh1 + (s - 12) * 16384;
        int tig = lane & 3, grp = lane >> 2;
        int k0 = ks * 16, n = nt * 8 + grp;
        float w0 = W[(k0 + 2 * tig)     * 128 + n];
        float w1 = W[(k0 + 2 * tig + 1) * 128 + n];
        float w2 = W[(k0 + 2 * tig + 8) * 128 + n];
        float w3 = W[(k0 + 2 * tig + 9) * 128 + n];
        unsigned h0, l0, h1, l1;
        bf16_split_pair(w0, w1, h0, l0);
        bf16_split_pair(w2, w3, h1, l1);
        g_Bp[idx] = make_uint4(h0, h1, l0, l1);
    } else {
        int i = (b - 256) * 256 + t;
        if (i < NNODES) { g_deg[i] = 1.0f; g_cnt[i] = 0; }   // self-loop weight 1
        if (i < NSB) g_bflag[i] = 0;
        if (b == 256) {
            __shared__ int nz;
            if (t == 0) nz = 0;
            __syncthreads();
            if (t < 128) {
                if (ei32[2 * t + 1] != 0) atomicAdd(&nz, 1);
            }
            __syncthreads();
            if (t == 0) g_is64 = (nz == 0) ? 1 : 0;
        }
    }
}

// ---------------- 4-edge decode ----------------
__device__ __forceinline__ void edge_decode4(const void* __restrict__ ei_raw, int e4,
                                             int* s, int* d) {
    if (g_is64) {
        const long long* ei = (const long long*)ei_raw;
        longlong2 s01 = *(const longlong2*)(ei + e4);
        longlong2 s23 = *(const longlong2*)(ei + e4 + 2);
        longlong2 d01 = *(const longlong2*)(ei + NEDGES + e4);
        longlong2 d23 = *(const longlong2*)(ei + NEDGES + e4 + 2);
        s[0] = (int)s01.x; s[1] = (int)s01.y; s[2] = (int)s23.x; s[3] = (int)s23.y;
        d[0] = (int)d01.x; d[1] = (int)d01.y; d[2] = (int)d23.x; d[3] = (int)d23.y;
    } else {
        const int* ei = (const int*)ei_raw;
        int4 sv = *(const int4*)(ei + e4);
        int4 dv = *(const int4*)(ei + NEDGES + e4);
        s[0] = sv.x; s[1] = sv.y; s[2] = sv.z; s[3] = sv.w;
        d[0] = dv.x; d[1] = dv.y; d[2] = dv.z; d[3] = dv.w;
    }
#pragma unroll
    for (int i = 0; i < 4; i++) {
        if ((unsigned)s[i] >= NNODES) s[i] = 0;
        if ((unsigned)d[i] >= NNODES) d[i] = 0;
    }
}

// ---------------- edge histograms (4 edges / thread) ----------------
__global__ void k_edge_prep(const void* __restrict__ ei_raw,
                            const float* __restrict__ w) {
    int e4 = (blockIdx.x * blockDim.x + threadIdx.x) * 4;
    if (e4 >= NEDGES) return;
    int s[4], d[4];
    edge_decode4(ei_raw, e4, s, d);
    float4 wv = *(const float4*)(w + e4);
    atomicAdd(&g_deg[d[0]], wv.x); atomicAdd(&g_cnt[d[0]], 1);
    atomicAdd(&g_deg[d[1]], wv.y); atomicAdd(&g_cnt[d[1]], 1);
    atomicAdd(&g_deg[d[2]], wv.z); atomicAdd(&g_cnt[d[2]], 1);
    atomicAdd(&g_deg[d[3]], wv.w); atomicAdd(&g_cnt[d[3]], 1);
}

// ---------------- fused scan with decoupled lookback (NSB blocks x 1024) ----------------
__global__ void k_scan() {
    int b = blockIdx.x, t = threadIdx.x;
    int lane = t & 31, wid = t >> 5;
    int base = b * NPB;
    int v = (t < NPB) ? g_cnt[base + t] : 0;
    // intra-warp inclusive scan
    int incl = v;
#pragma unroll
    for (int off = 1; off < 32; off <<= 1) {
        int n = __shfl_up_sync(0xFFFFFFFFu, incl, off);
        if (lane >= off) incl += n;
    }
    __shared__ int wsum[32];
    __shared__ int sbase;
    if (lane == 31) wsum[wid] = incl;
    __syncthreads();
    if (wid == 0) {
        int wv = wsum[lane];
        int wi = wv;
#pragma unroll
        for (int off = 1; off < 32; off <<= 1) {
            int n = __shfl_up_sync(0xFFFFFFFFu, wi, off);
            if (lane >= off) wi += n;
        }
        wsum[lane] = wi - wv;   // exclusive warp base
        int total = __shfl_sync(0xFFFFFFFFu, wi, 31);
        if (lane == 0) {
            g_bsum_v[b] = total;
            __threadfence();
            g_bflag[b] = 1;
        }
        // lookback: gather predecessor block sums
        int x = 0;
        if (lane < b) {
            while (g_bflag[lane] == 0) {}
            x = g_bsum_v[lane];
        }
        __syncwarp();
#pragma unroll
        for (int off = 16; off > 0; off >>= 1) x += __shfl_down_sync(0xFFFFFFFFu, x, off);
        if (lane == 0) sbase = x;
    }
    __syncthreads();
    if (t < NPB) {
        int excl = sbase + wsum[wid] + incl - v;
        g_rowptr[base + t] = excl;
        g_cur[base + t] = excl;
        float dg = g_deg[base + t];
        g_dis[base + t] = dg > 0.f ? rsqrtf(fmaxf(dg, 1e-12f)) : 0.f;
    }
    if (b == NSB - 1 && t == 0) g_rowptr[NNODES] = NEDGES;
}

// ---------------- scatter edges into CSR + compute norm (4 edges / thread) ----------------
__global__ void k_scatter(const void* __restrict__ ei_raw, const float* __restrict__ w) {
    int e4 = (blockIdx.x * blockDim.x + threadIdx.x) * 4;
    if (e4 >= NEDGES) return;
    int s[4], d[4];
    edge_decode4(ei_raw, e4, s, d);
    float4 wv = *(const float4*)(w + e4);
    float wa[4] = {wv.x, wv.y, wv.z, wv.w};
#pragma unroll
    for (int i = 0; i < 4; i++) {
        int pos = atomicAdd(&g_cur[d[i]], 1);
        g_ecol[pos] = s[i];
        g_enorm[pos] = g_dis[s[i]] * wa[i] * g_dis[d[i]];
    }
}

// ---------------- fused gather SpMM for x and h (F=128), one warp per node ----------------
__global__ void k_gather_xh(const float* __restrict__ x, const float* __restrict__ h) {
    int warp = (blockIdx.x * blockDim.x + threadIdx.x) >> 5;
    int lane = threadIdx.x & 31;
    if (warp >= NNODES) return;
    int n = warp;
    float sd = g_dis[n];
    float s2 = sd * sd;
    float4 xv = *((const float4*)(x + (size_t)n * HD) + lane);
    float4 hv = *((const float4*)(h + (size_t)n * HD) + lane);
    float4 ax = make_float4(s2 * xv.x, s2 * xv.y, s2 * xv.z, s2 * xv.w);
    float4 ah = make_float4(s2 * hv.x, s2 * hv.y, s2 * hv.z, s2 * hv.w);
    int e0 = g_rowptr[n], e1 = g_rowptr[n + 1];
#pragma unroll 4
    for (int e = e0; e < e1; ++e) {
        int c = g_ecol[e];
        float nm = g_enorm[e];
        float4 cx = *((const float4*)(x + (size_t)c * HD) + lane);
        float4 ch = *((const float4*)(h + (size_t)c * HD) + lane);
        ax.x = fmaf(nm, cx.x, ax.x); ax.y = fmaf(nm, cx.y, ax.y);
        ax.z = fmaf(nm, cx.z, ax.z); ax.w = fmaf(nm, cx.w, ax.w);
        ah.x = fmaf(nm, ch.x, ah.x); ah.y = fmaf(nm, ch.y, ah.y);
        ah.z = fmaf(nm, ch.z, ah.z); ah.w = fmaf(nm, ch.w, ah.w);
    }
    ((float4*)(g_ax + (size_t)n * HD))[lane] = ax;
    ((float4*)(g_ah + (size_t)n * HD))[lane] = ah;
}

// ---------------- tensor-core GEMM building blocks (m16n8k16 bf16, 3-term split) ----------------
#define MMA_BF16(c, a, bb0, bb1) \
    asm("mma.sync.aligned.m16n8k16.row.col.f32.bf16.bf16.f32 " \
        "{%0,%1,%2,%3},{%4,%5,%6,%7},{%8,%9},{%0,%1,%2,%3};" \
        : "+f"(c[0]), "+f"(c[1]), "+f"(c[2]), "+f"(c[3]) \
        : "r"(a[0]), "r"(a[1]), "r"(a[2]), "r"(a[3]), "r"(bb0), "r"(bb1))

// volatile + memory clobber: the load must NOT be reordered across __syncthreads()
// or the shared-memory staging stores (buffers are re-staged / overwritten between passes).
#define LDSM_X4(r, addr) \
    asm volatile("ldmatrix.sync.aligned.m8n8.x4.shared.b16 {%0,%1,%2,%3}, [%4];" \
        : "=r"(r[0]), "=r"(r[1]), "=r"(r[2]), "=r"(r[3]) : "r"(addr) : "memory")

// stage a 128x128 fp32 tile from global, split into hi/lo bf16x2-pair smem arrays
__device__ __forceinline__ void stage_split(const float* __restrict__ A, int lda, int row0,
                                            unsigned* hi_arr, unsigned* lo_arr) {
    int tid = threadIdx.x;
    float4 v[16];
#pragma unroll
    for (int i = 0; i < 16; i++) {
        int f = i * 256 + tid;            // 0..4095
        int row = f >> 5;                 // 0..127
        int c4 = (f & 31) * 4;            // 0..124
        int grow = row0 + row;
        v[i] = (grow < NNODES) ? *(const float4*)(A + (size_t)grow * lda + c4)
                               : make_float4(0.f, 0.f, 0.f, 0.f);
    }
#pragma unroll
    for (int i = 0; i < 16; i++) {
        int f = i * 256 + tid;
        int row = f >> 5;
        int pc = (f & 31) * 2;            // pair column (even)
        unsigned h0, l0, h1, l1;
        bf16_split_pair(v[i].x, v[i].y, h0, l0);
        bf16_split_pair(v[i].z, v[i].w, h1, l1);
        hi_arr[row * FSTR + pc] = h0; hi_arr[row * FSTR + pc + 1] = h1;
        lo_arr[row * FSTR + pc] = l0; lo_arr[row * FSTR + pc + 1] = l1;
    }
}

// acc += (smem A tile) @ (pre-split B stream), 3-term split; A frags via ldmatrix
__device__ __forceinline__ void mma_pass(float (*acc)[4][4],
                                         const unsigned* As_hi, const unsigned* As_lo,
                                         int stream) {
    int tid = threadIdx.x;
    int wid = tid >> 5, lane = tid & 31;
    int wm = wid >> 2, wn = wid & 3;
    int m0 = wm * 64;
    const uint4* __restrict__ Bp = g_Bp + (stream << 12);
    // ldmatrix lane->address map: lanes 0-7: rows 0-7 (k-low); 8-15: rows 8-15 (k-low);
    // 16-23: rows 0-7 (k-high); 24-31: rows 8-15 (k-high)
    int lrow = (lane & 7) + ((lane >> 3) & 1) * 8;
    int lcol = (lane >> 4) * 4;
    unsigned hi_base = (unsigned)__cvta_generic_to_shared(As_hi)
                     + ((m0 + lrow) * FSTR + lcol) * 4;
    unsigned lo_base = (unsigned)__cvta_generic_to_shared(As_lo)
                     + ((m0 + lrow) * FSTR + lcol) * 4;
#pragma unroll
    for (int ks = 0; ks < 8; ks++) {
        unsigned ahi[4][4], alo[4][4];
#pragma unroll
        for (int mt = 0; mt < 4; mt++) {
            unsigned off = (mt * 16 * FSTR + ks * 8) * 4;
            LDSM_X4(ahi[mt], hi_base + off);
            LDSM_X4(alo[mt], lo_base + off);
        }
#pragma unroll
        for (int nt = 0; nt < 4; nt++) {
            uint4 b = Bp[(ks * 16 + wn * 4 + nt) * 32 + lane];
#pragma unroll
            for (int mt = 0; mt < 4; mt++) {
                float* c = acc[mt][nt];
                MMA_BF16(c, ahi[mt], b.x, b.y);   // hi*hi
                MMA_BF16(c, ahi[mt], b.z, b.w);   // hi*lo
                MMA_BF16(c, alo[mt], b.x, b.y);   // lo*hi
            }
        }
    }
}

// relu(acc + bias) -> split -> z smem buffers (C-frag pair (c0,c1) is an adjacent k-pair)
__device__ __forceinline__ void store_z(float (*acc)[4][4], const float* __restrict__ bias,
                                        unsigned* zhi, unsigned* zlo) {
    int tid = threadIdx.x;
    int wid = tid >> 5, lane = tid & 31;
    int wm = wid >> 2, wn = wid & 3;
    int m0 = wm * 64, n0 = wn * 32;
    int tig = lane & 3, grp = lane >> 2;
#pragma unroll
    for (int nt = 0; nt < 4; nt++) {
        int col = n0 + nt * 8 + 2 * tig;
        float b0 = bias[col], b1 = bias[col + 1];
        int pc = col >> 1;
#pragma unroll
        for (int mt = 0; mt < 4; mt++) {
            int r = m0 + mt * 16 + grp;
            float* c = acc[mt][nt];
            float u0 = fmaxf(c[0] + b0, 0.f), u1 = fmaxf(c[1] + b1, 0.f);
            float u2 = fmaxf(c[2] + b0, 0.f), u3 = fmaxf(c[3] + b1, 0.f);
            unsigned h, l;
            bf16_split_pair(u0, u1, h, l);
            zhi[r * FSTR + pc] = h; zlo[r * FSTR + pc] = l;
            bf16_split_pair(u2, u3, h, l);
            zhi[(r + 8) * FSTR + pc] = h; zlo[(r + 8) * FSTR + pc] = l;
        }
    }
}

__device__ __forceinline__ void gemm_epilogue_y(float (*acc)[4][4],
                                                float* __restrict__ C, int ldc, int row0) {
    int tid = threadIdx.x;
    int wid = tid >> 5, lane = tid & 31;
    int wm = wid >> 2, wn = wid & 3;
    int m0 = wm * 64, n0 = wn * 32;
    int tig = lane & 3, grp = lane >> 2;
#pragma unroll
    for (int nt = 0; nt < 4; nt++) {
        int col = n0 + nt * 8 + 2 * tig;
#pragma unroll
        for (int mt = 0; mt < 4; mt++) {
            int r = row0 + m0 + mt * 16 + grp;
            float* c = acc[mt][nt];
            if (r < NNODES)
                *(float2*)&C[(size_t)r * ldc + col] = make_float2(c[0], c[1]);
            int r2 = r + 8;
            if (r2 < NNODES)
                *(float2*)&C[(size_t)r2 * ldc + col] = make_float2(c[2], c[3]);
        }
    }
}

// fused 2-layer GEMM per (gate, row-tile): z never leaves the SM.
// Pipeline: stage BOTH A tiles up front (h-branch loads overlap x-branch MMA).
__global__ __launch_bounds__(256) void k_mma_fused(const float* __restrict__ bx0,
                                                   const float* __restrict__ bh0) {
    extern __shared__ unsigned sm[];
    unsigned *Ah  = sm,            *Al  = sm + ZOFF;
    unsigned *zxh = sm + 2 * ZOFF, *zxl = sm + 3 * ZOFF;
    unsigned *zhh = sm + 4 * ZOFF, *zhl = sm + 5 * ZOFF;
    int g = blockIdx.y;
    int row0 = blockIdx.x * 128;

    // stage x -> (Ah,Al) and h -> (zhh,zhl) [h staging overlaps x MMA below]
    stage_split(g_ax, 128, row0, Ah, Al);
    stage_split(g_ah, 128, row0, zhh, zhl);
    __syncthreads();

    // layer-1 x-branch: z_x = relu(ax @ Wx0[g] + bx0[g])
    float accz[4][4][4];
#pragma unroll
    for (int a = 0; a < 4; a++)
#pragma unroll
        for (int b = 0; b < 4; b++)
#pragma unroll
            for (int cc = 0; cc < 4; cc++) accz[a][b][cc] = 0.f;
    mma_pass(accz, Ah, Al, g);
    store_z(accz, bx0 + g * 128, zxh, zxl);

    // layer-1 h-branch: A-h already staged in (zhh,zhl)
    float acch[4][4][4];
#pragma unroll
    for (int a = 0; a < 4; a++)
#pragma unroll
        for (int b = 0; b < 4; b++)
#pragma unroll
            for (int cc = 0; cc < 4; cc++) acch[a][b][cc] = 0.f;
    mma_pass(acch, zhh, zhl, 4 + g);
    __syncthreads();    // all warps finished reading A-h (and zxh writes now visible)
    store_z(acch, bh0 + g * 128, zhh, zhl);   // overwrite A-h with z_h
    __syncthreads();    // z_h visible

    // layer-2: y = z_x @ Wx1[g] + z_h @ Wh1[g]   (bias deferred to LSTM)
    float accy[4][4][4];
#pragma unroll
    for (int a = 0; a < 4; a++)
#pragma unroll
        for (int b = 0; b < 4; b++)
#pragma unroll
            for (int cc = 0; cc < 4; cc++) accy[a][b][cc] = 0.f;
    mma_pass(accy, zxh, zxl, 8 + g);
    mma_pass(accy, zhh, zhl, 12 + g);
    gemm_epilogue_y(accy, g_y + g * 128, 512, row0);
}

// ---------------- fused F=512 gather + LSTM epilogue: one block (128 thr) per node ----------------
__device__ __forceinline__ float sigmoidf_(float v) { return 1.f / (1.f + expf(-v)); }

__global__ void __launch_bounds__(128) k_gather_lstm(
    const float* __restrict__ c,
    const float* __restrict__ bx1, const float* __restrict__ bh1,
    const float* __restrict__ wc, const float* __restrict__ bg,
    float* __restrict__ out)
{
    __shared__ float sG[512];
    int n = blockIdx.x;
    int t = threadIdx.x;
    float sd = g_dis[n];
    float s2 = sd * sd;
    float4 v = ((const float4*)(g_y + (size_t)n * 512))[t];
    float4 acc = make_float4(s2 * v.x, s2 * v.y, s2 * v.z, s2 * v.w);
    int e0 = g_rowptr[n], e1 = g_rowptr[n + 1];
#pragma unroll 4
    for (int e = e0; e < e1; ++e) {
        int cc = g_ecol[e];
        float nm = g_enorm[e];
        float4 yv = ((const float4*)(g_y + (size_t)cc * 512))[t];
        acc.x = fmaf(nm, yv.x, acc.x); acc.y = fmaf(nm, yv.y, acc.y);
        acc.z = fmaf(nm, yv.z, acc.z); acc.w = fmaf(nm, yv.w, acc.w);
    }
    ((float4*)sG)[t] = acc;
    __syncthreads();
    int f = t;
    int idx = n * HD + f;
    float cv = c[idx];
    float Gi = sG[f]       + bx1[f]       + bh1[f];
    float Gf = sG[128 + f] + bx1[128 + f] + bh1[128 + f];
    float Gc = sG[256 + f] + bx1[256 + f] + bh1[256 + f];
    float Go = sG[384 + f] + bx1[384 + f] + bh1[384 + f];
    float I  = sigmoidf_(Gi + wc[f] * cv + bg[f]);
    float Fg = sigmoidf_(Gf + wc[128 + f] * cv + bg[128 + f]);
    float T  = tanhf(Gc + bg[256 + f]);
    float Cn = Fg * cv + I * T;
    float O  = sigmoidf_(Go + wc[256 + f] * Cn + bg[384 + f]);
    float Hn = O * tanhf(Cn);
    out[idx] = Hn;
    out[(size_t)NNODES * HD + idx] = Cn;
}

// ---------------- launch ----------------
extern "C" void kernel_launch(void* const* d_in, const int* in_sizes, int n_in,
                              void* d_out, int out_size) {
    const float* x   = (const float*)d_in[0];
    const void*  ei  = d_in[1];                 // int32 or int64, detected on device
    const float* w   = (const float*)d_in[2];
    const float* h   = (const float*)d_in[3];
    const float* c   = (const float*)d_in[4];
    const float* Wx0 = (const float*)d_in[5];
    const float* bx0 = (const float*)d_in[6];
    const float* Wx1 = (const float*)d_in[7];
    const float* bx1 = (const float*)d_in[8];
    const float* Wh0 = (const float*)d_in[9];
    const float* bh0 = (const float*)d_in[10];
    const float* Wh1 = (const float*)d_in[11];
    const float* bh1 = (const float*)d_in[12];
    const float* wc  = (const float*)d_in[13];
    const float* bg  = (const float*)d_in[14];
    float* out = (float*)d_out;

    static int smem_set = 0;
    if (!smem_set) {
        cudaFuncSetAttribute(k_mma_fused, cudaFuncAttributeMaxDynamicSharedMemorySize,
                             SMEM_FUSED_BYTES);
        smem_set = 1;
    }

    const int T = 256;
    // prologue: merged init+wprep, edge hist, fused lookback scan, CSR scatter
    k_init_wprep<<<256 + (NNODES + T - 1) / T, T>>>((const int*)ei, Wx0, Wh0, Wx1, Wh1);
    k_edge_prep<<<(NEDGES / 4 + T - 1) / T, T>>>(ei, w);
    k_scan<<<NSB, 1024>>>();
    k_scatter<<<(NEDGES / 4 + T - 1) / T, T>>>(ei, w);

    // fused first props (F=128) for x and h, gather-based
    k_gather_xh<<<(NNODES * 32 + T - 1) / T, T>>>(x, h);

    // fused 2-layer tensor-core GEMM (z stays on-chip)
    dim3 gm((NNODES + 127) / 128, 4);
    k_mma_fused<<<gm, 256, SMEM_FUSED_BYTES>>>(bx0, bh0);

    // fused F=512 gather + LSTM epilogue
    k_gather_lstm<<<NNODES, 128>>>(c, bx1, bh1, wc, bg, out);
}

// round 12
// speedup vs baseline: 5.4283x; 1.0247x over previous
#include <cuda_runtime.h>
#include <cuda_fp16.h>
#include <math.h>

#define NNODES 20000
#define NEDGES 320000
#define HD 128
#define FSTR 68                  // pair-column stride (words), conflict-free
#define ZOFF (128 * FSTR)        // words per hi/lo array
#define SMEM_FUSED_BYTES (6 * ZOFF * 4)   // As + zx + zh, hi+lo each = 208896 B
#define NPB 1000                 // nodes per scan block
#define NSB 20                   // scan blocks

// ---------------- scratch (static device allocations) ----------------
__device__ int   g_is64;
__device__ volatile int g_sync1;
__device__ volatile int g_sync2;
__device__ __align__(16) float g_deg[NNODES];
__device__ __align__(16) int   g_cnt[NNODES];
__device__ volatile int g_bsum_v[NSB];
__device__ volatile int g_bflag[NSB];
__device__ __align__(16) int   g_rowptr[NNODES + 4];
__device__ __align__(16) int   g_cur[NNODES + 4];
__device__ __align__(16) float g_dis[NNODES];
__device__ __align__(16) int   g_ecol[NEDGES];    // CSR (by dst): src node
__device__ __align__(16) float g_enorm[NEDGES];   // CSR (by dst): edge norm
__device__ __align__(16) float g_ax[(size_t)NNODES * HD];   // prop(x)
__device__ __align__(16) float g_ah[(size_t)NNODES * HD];   // prop(h)
__device__ __align__(16) __half g_y16[(size_t)NNODES * 512]; // pre-prop gate features (fp16)
// pre-split bf16 weights: [stream 16][ks 8][nt 16][lane 32] = (hi0,hi1,lo0,lo1)
__device__ __align__(16) uint4 g_Bp[16 * 8 * 16 * 32];

// bf16 truncation split of a k-pair (x0=even k, x1=odd k) into packed bf16x2 regs.
__device__ __forceinline__ void bf16_split_pair(float x0, float x1,
                                                unsigned &hi, unsigned &lo) {
    unsigned b0 = __float_as_uint(x0), b1 = __float_as_uint(x1);
    hi = __byte_perm(b0, b1, 0x7632);              // {lo16=top16(x0), hi16=top16(x1)}
    float l0 = x0 - __uint_as_float(b0 & 0xFFFF0000u);
    float l1 = x1 - __uint_as_float(b1 & 0xFFFF0000u);
    asm("cvt.rn.bf16x2.f32 %0, %1, %2;" : "=r"(lo) : "f"(l1), "f"(l0));
}

// ---------------- merged init (deg/cnt/flags/sync + dtype detect) + weight prep ----------------
// blocks 0..255: wprep; blocks 256..334: init; block 256 also runs dtype detect.
__global__ void k_init_wprep(const int* __restrict__ ei32,
                             const float* __restrict__ Wx0, const float* __restrict__ Wh0,
                             const float* __restrict__ Wx1, const float* __restrict__ Wh1) {
    int b = blockIdx.x, t = threadIdx.x;
    if (b < 256) {
        int idx = b * 256 + t;            // 0..65535
        int s    = idx >> 12;             // stream
        int ks   = (idx >> 9) & 7;        // k-step (k0 = ks*16)
        int nt   = (idx >> 5) & 15;       // n-tile (n0 = nt*8)
        int lane = idx & 31;
        const float* W;
        if (s < 4)       W = Wx0 + s * 16384;
        else if (s < 8)  W = Wh0 + (s - 4) * 16384;
        else if (s < 12) W = Wx1 + (s - 8) * 16384;
        else             W = Wh1 + (s - 12) * 16384;
        int tig = lane & 3, grp = lane >> 2;
        int k0 = ks * 16, n = nt * 8 + grp;
        float w0 = W[(k0 + 2 * tig)     * 128 + n];
        float w1 = W[(k0 + 2 * tig + 1) * 128 + n];
        float w2 = W[(k0 + 2 * tig + 8) * 128 + n];
        float w3 = W[(k0 + 2 * tig + 9) * 128 + n];
        unsigned h0, l0, h1, l1;
        bf16_split_pair(w0, w1, h0, l0);
        bf16_split_pair(w2, w3, h1, l1);
        g_Bp[idx] = make_uint4(h0, h1, l0, l1);
    } else {
        int i = (b - 256) * 256 + t;
        if (i < NNODES) { g_deg[i] = 1.0f; g_cnt[i] = 0; }   // self-loop weight 1
        if (i < NSB) { g_bflag[i] = 0; }
        if (i == 0) { g_sync1 = 0; g_sync2 = 0; }
        if (b == 256) {
            __shared__ int nz;
            if (t == 0) nz = 0;
            __syncthreads();
            if (t < 128) {
                if (ei32[2 * t + 1] != 0) atomicAdd(&nz, 1);
            }
            __syncthreads();
            if (t == 0) g_is64 = (nz == 0) ? 1 : 0;
        }
    }
}

// ---------------- 4-edge decode ----------------
__device__ __forceinline__ void edge_decode4(const void* __restrict__ ei_raw, int e4,
                                             int* s, int* d) {
    if (g_is64) {
        const long long* ei = (const long long*)ei_raw;
        longlong2 s01 = *(const longlong2*)(ei + e4);
        longlong2 s23 = *(const longlong2*)(ei + e4 + 2);
        longlong2 d01 = *(const longlong2*)(ei + NEDGES + e4);
        longlong2 d23 = *(const longlong2*)(ei + NEDGES + e4 + 2);
        s[0] = (int)s01.x; s[1] = (int)s01.y; s[2] = (int)s23.x; s[3] = (int)s23.y;
        d[0] = (int)d01.x; d[1] = (int)d01.y; d[2] = (int)d23.x; d[3] = (int)d23.y;
    } else {
        const int* ei = (const int*)ei_raw;
        int4 sv = *(const int4*)(ei + e4);
        int4 dv = *(const int4*)(ei + NEDGES + e4);
        s[0] = sv.x; s[1] = sv.y; s[2] = sv.z; s[3] = sv.w;
        d[0] = dv.x; d[1] = dv.y; d[2] = dv.z; d[3] = dv.w;
    }
#pragma unroll
    for (int i = 0; i < 4; i++) {
        if ((unsigned)s[i] >= NNODES) s[i] = 0;
        if ((unsigned)d[i] >= NNODES) d[i] = 0;
    }
}

// ---------------- single-kernel edge pipeline: histogram -> scan -> scatter ----------------
// grid 313 x 256 (single wave, co-resident -> software grid barriers are safe).
__global__ void __launch_bounds__(256) k_edges(const void* __restrict__ ei_raw,
                                               const float* __restrict__ w) {
    int b = blockIdx.x, t = threadIdx.x;
    int lane = t & 31, wid = t >> 5;
    int e4 = (b * 256 + t) * 4;
    bool ev = (e4 < NEDGES);
    int s[4], d[4];
    float4 wv = make_float4(0.f, 0.f, 0.f, 0.f);

    // phase 1: decode + histogram
    if (ev) {
        edge_decode4(ei_raw, e4, s, d);
        wv = *(const float4*)(w + e4);
        atomicAdd(&g_deg[d[0]], wv.x); atomicAdd(&g_cnt[d[0]], 1);
        atomicAdd(&g_deg[d[1]], wv.y); atomicAdd(&g_cnt[d[1]], 1);
        atomicAdd(&g_deg[d[2]], wv.z); atomicAdd(&g_cnt[d[2]], 1);
        atomicAdd(&g_deg[d[3]], wv.w); atomicAdd(&g_cnt[d[3]], 1);
    }
    // grid barrier 1
    __syncthreads();
    if (t == 0) {
        __threadfence();
        atomicAdd((int*)&g_sync1, 1);
        while (g_sync1 < (int)gridDim.x) {}
    }
    __syncthreads();

    // phase 2a: scan (blocks < NSB), 256 threads x 4 nodes
    __shared__ int wsum[8];
    __shared__ int sbase;
    if (b < NSB) {
        int base = b * NPB;
        bool act = (t < NPB / 4);          // t < 250
        int4 q = make_int4(0, 0, 0, 0);
        int tsum = 0;
        if (act) {
            q = *(const int4*)(g_cnt + base + 4 * t);
            tsum = q.x + q.y + q.z + q.w;
        }
        int incl = tsum;
#pragma unroll
        for (int off = 1; off < 32; off <<= 1) {
            int n = __shfl_up_sync(0xFFFFFFFFu, incl, off);
            if (lane >= off) incl += n;
        }
        if (lane == 31) wsum[wid] = incl;
        __syncthreads();
        if (t < 8) {
            int wv2 = wsum[t], wi = wv2;
#pragma unroll
            for (int off = 1; off < 8; off <<= 1) {
                int n = __shfl_up_sync(0xFFu, wi, off);
                if (t >= off) wi += n;
            }
            wsum[t] = wi - wv2;            // exclusive warp base
            if (t == 7) {
                g_bsum_v[b] = wi;          // block total
                __threadfence();
                g_bflag[b] = 1;
            }
        }
        if (wid == 0) {                    // decoupled lookback
            int xx = 0;
            if (lane < b) {
                while (g_bflag[lane] == 0) {}
                xx = g_bsum_v[lane];
            }
            __syncwarp();
#pragma unroll
            for (int off = 16; off > 0; off >>= 1) xx += __shfl_down_sync(0xFFFFFFFFu, xx, off);
            if (lane == 0) sbase = xx;
        }
        __syncthreads();
        if (act) {
            int excl = sbase + wsum[wid] + incl - tsum;
            int4 rp = make_int4(excl, excl + q.x, excl + q.x + q.y, excl + q.x + q.y + q.z);
            *(int4*)(g_rowptr + base + 4 * t) = rp;
            *(int4*)(g_cur + base + 4 * t) = rp;
        }
        if (b == NSB - 1 && t == 0) g_rowptr[NNODES] = NEDGES;
    }
    // phase 2b: dis (all blocks, 64 nodes each; 313*64 >= 20000)
    if (t < 64) {
        int i = b * 64 + t;
        if (i < NNODES) {
            float dg = g_deg[i];
            g_dis[i] = dg > 0.f ? rsqrtf(fmaxf(dg, 1e-12f)) : 0.f;
        }
    }
    // grid barrier 2
    __syncthreads();
    if (t == 0) {
        __threadfence();
        atomicAdd((int*)&g_sync2, 1);
        while (g_sync2 < (int)gridDim.x) {}
    }
    __syncthreads();

    // phase 3: scatter (indices still in registers)
    if (ev) {
        float wa[4] = {wv.x, wv.y, wv.z, wv.w};
#pragma unroll
        for (int i = 0; i < 4; i++) {
            int pos = atomicAdd(&g_cur[d[i]], 1);
            g_ecol[pos] = s[i];
            g_enorm[pos] = g_dis[s[i]] * wa[i] * g_dis[d[i]];
        }
    }
}

// ---------------- fused gather SpMM for x and h (F=128), one warp per node ----------------
__global__ void k_gather_xh(const float* __restrict__ x, const float* __restrict__ h) {
    int warp = (blockIdx.x * blockDim.x + threadIdx.x) >> 5;
    int lane = threadIdx.x & 31;
    if (warp >= NNODES) return;
    int n = warp;
    float sd = g_dis[n];
    float s2 = sd * sd;
    float4 xv = *((const float4*)(x + (size_t)n * HD) + lane);
    float4 hv = *((const float4*)(h + (size_t)n * HD) + lane);
    float4 ax = make_float4(s2 * xv.x, s2 * xv.y, s2 * xv.z, s2 * xv.w);
    float4 ah = make_float4(s2 * hv.x, s2 * hv.y, s2 * hv.z, s2 * hv.w);
    int e0 = g_rowptr[n], e1 = g_rowptr[n + 1];
#pragma unroll 4
    for (int e = e0; e < e1; ++e) {
        int c = g_ecol[e];
        float nm = g_enorm[e];
        float4 cx = *((const float4*)(x + (size_t)c * HD) + lane);
        float4 ch = *((const float4*)(h + (size_t)c * HD) + lane);
        ax.x = fmaf(nm, cx.x, ax.x); ax.y = fmaf(nm, cx.y, ax.y);
        ax.z = fmaf(nm, cx.z, ax.z); ax.w = fmaf(nm, cx.w, ax.w);
        ah.x = fmaf(nm, ch.x, ah.x); ah.y = fmaf(nm, ch.y, ah.y);
        ah.z = fmaf(nm, ch.z, ah.z); ah.w = fmaf(nm, ch.w, ah.w);
    }
    ((float4*)(g_ax + (size_t)n * HD))[lane] = ax;
    ((float4*)(g_ah + (size_t)n * HD))[lane] = ah;
}

// ---------------- tensor-core GEMM building blocks (m16n8k16 bf16, 3-term split) ----------------
#define MMA_BF16(c, a, bb0, bb1) \
    asm("mma.sync.aligned.m16n8k16.row.col.f32.bf16.bf16.f32 " \
        "{%0,%1,%2,%3},{%4,%5,%6,%7},{%8,%9},{%0,%1,%2,%3};" \
        : "+f"(c[0]), "+f"(c[1]), "+f"(c[2]), "+f"(c[3]) \
        : "r"(a[0]), "r"(a[1]), "r"(a[2]), "r"(a[3]), "r"(bb0), "r"(bb1))

// volatile + memory clobber: the load must NOT be reordered across __syncthreads()
// or the shared-memory staging stores (buffers are re-staged / overwritten between passes).
#define LDSM_X4(r, addr) \
    asm volatile("ldmatrix.sync.aligned.m8n8.x4.shared.b16 {%0,%1,%2,%3}, [%4];" \
        : "=r"(r[0]), "=r"(r[1]), "=r"(r[2]), "=r"(r[3]) : "r"(addr) : "memory")

// stage a 128x128 fp32 tile from global, split into hi/lo bf16x2-pair smem arrays
__device__ __forceinline__ void stage_split(const float* __restrict__ A, int lda, int row0,
                                            unsigned* hi_arr, unsigned* lo_arr) {
    int tid = threadIdx.x;
    float4 v[16];
#pragma unroll
    for (int i = 0; i < 16; i++) {
        int f = i * 256 + tid;            // 0..4095
        int row = f >> 5;                 // 0..127
        int c4 = (f & 31) * 4;            // 0..124
        int grow = row0 + row;
        v[i] = (grow < NNODES) ? *(const float4*)(A + (size_t)grow * lda + c4)
                               : make_float4(0.f, 0.f, 0.f, 0.f);
    }
#pragma unroll
    for (int i = 0; i < 16; i++) {
        int f = i * 256 + tid;
        int row = f >> 5;
        int pc = (f & 31) * 2;            // pair column (even)
        unsigned h0, l0, h1, l1;
        bf16_split_pair(v[i].x, v[i].y, h0, l0);
        bf16_split_pair(v[i].z, v[i].w, h1, l1);
        hi_arr[row * FSTR + pc] = h0; hi_arr[row * FSTR + pc + 1] = h1;
        lo_arr[row * FSTR + pc] = l0; lo_arr[row * FSTR + pc + 1] = l1;
    }
}

// acc += (smem A tile) @ (pre-split B stream), 3-term split; A frags via ldmatrix
__device__ __forceinline__ void mma_pass(float (*acc)[4][4],
                                         const unsigned* As_hi, const unsigned* As_lo,
                                         int stream) {
    int tid = threadIdx.x;
    int wid = tid >> 5, lane = tid & 31;
    int wm = wid >> 2, wn = wid & 3;
    int m0 = wm * 64;
    const uint4* __restrict__ Bp = g_Bp + (stream << 12);
    int lrow = (lane & 7) + ((lane >> 3) & 1) * 8;
    int lcol = (lane >> 4) * 4;
    unsigned hi_base = (unsigned)__cvta_generic_to_shared(As_hi)
                     + ((m0 + lrow) * FSTR + lcol) * 4;
    unsigned lo_base = (unsigned)__cvta_generic_to_shared(As_lo)
                     + ((m0 + lrow) * FSTR + lcol) * 4;
#pragma unroll
    for (int ks = 0; ks < 8; ks++) {
        unsigned ahi[4][4], alo[4][4];
#pragma unroll
        for (int mt = 0; mt < 4; mt++) {
            unsigned off = (mt * 16 * FSTR + ks * 8) * 4;
            LDSM_X4(ahi[mt], hi_base + off);
            LDSM_X4(alo[mt], lo_base + off);
        }
#pragma unroll
        for (int nt = 0; nt < 4; nt++) {
            uint4 b = Bp[(ks * 16 + wn * 4 + nt) * 32 + lane];
#pragma unroll
            for (int mt = 0; mt < 4; mt++) {
                float* c = acc[mt][nt];
                MMA_BF16(c, ahi[mt], b.x, b.y);   // hi*hi
                MMA_BF16(c, ahi[mt], b.z, b.w);   // hi*lo
                MMA_BF16(c, alo[mt], b.x, b.y);   // lo*hi
            }
        }
    }
}

// relu(acc + bias) -> split -> z smem buffers (C-frag pair (c0,c1) is an adjacent k-pair)
__device__ __forceinline__ void store_z(float (*acc)[4][4], const float* __restrict__ bias,
                                        unsigned* zhi, unsigned* zlo) {
    int tid = threadIdx.x;
    int wid = tid >> 5, lane = tid & 31;
    int wm = wid >> 2, wn = wid & 3;
    int m0 = wm * 64, n0 = wn * 32;
    int tig = lane & 3, grp = lane >> 2;
#pragma unroll
    for (int nt = 0; nt < 4; nt++) {
        int col = n0 + nt * 8 + 2 * tig;
        float b0 = bias[col], b1 = bias[col + 1];
        int pc = col >> 1;
#pragma unroll
        for (int mt = 0; mt < 4; mt++) {
            int r = m0 + mt * 16 + grp;
            float* c = acc[mt][nt];
            float u0 = fmaxf(c[0] + b0, 0.f), u1 = fmaxf(c[1] + b1, 0.f);
            float u2 = fmaxf(c[2] + b0, 0.f), u3 = fmaxf(c[3] + b1, 0.f);
            unsigned h, l;
            bf16_split_pair(u0, u1, h, l);
            zhi[r * FSTR + pc] = h; zlo[r * FSTR + pc] = l;
            bf16_split_pair(u2, u3, h, l);
            zhi[(r + 8) * FSTR + pc] = h; zlo[(r + 8) * FSTR + pc] = l;
        }
    }
}

// write y as fp16 (halves gather traffic downstream)
__device__ __forceinline__ void gemm_epilogue_y16(float (*acc)[4][4],
                                                  __half* __restrict__ C, int ldc, int row0) {
    int tid = threadIdx.x;
    int wid = tid >> 5, lane = tid & 31;
    int wm = wid >> 2, wn = wid & 3;
    int m0 = wm * 64, n0 = wn * 32;
    int tig = lane & 3, grp = lane >> 2;
#pragma unroll
    for (int nt = 0; nt < 4; nt++) {
        int col = n0 + nt * 8 + 2 * tig;
#pragma unroll
        for (int mt = 0; mt < 4; mt++) {
            int r = row0 + m0 + mt * 16 + grp;
            float* c = acc[mt][nt];
            if (r < NNODES)
                *(__half2*)(C + (size_t)r * ldc + col) = __floats2half2_rn(c[0], c[1]);
            int r2 = r + 8;
            if (r2 < NNODES)
                *(__half2*)(C + (size_t)r2 * ldc + col) = __floats2half2_rn(c[2], c[3]);
        }
    }
}

// fused 2-layer GEMM per (gate, row-tile): z never leaves the SM.
__global__ __launch_bounds__(256) void k_mma_fused(const float* __restrict__ bx0,
                                                   const float* __restrict__ bh0) {
    extern __shared__ unsigned sm[];
    unsigned *Ah  = sm,            *Al  = sm + ZOFF;
    unsigned *zxh = sm + 2 * ZOFF, *zxl = sm + 3 * ZOFF;
    unsigned *zhh = sm + 4 * ZOFF, *zhl = sm + 5 * ZOFF;
    int g = blockIdx.y;
    int row0 = blockIdx.x * 128;

    // stage x -> (Ah,Al) and h -> (zhh,zhl) [h staging overlaps x MMA below]
    stage_split(g_ax, 128, row0, Ah, Al);
    stage_split(g_ah, 128, row0, zhh, zhl);
    __syncthreads();

    // layer-1 x-branch
    float accz[4][4][4];
#pragma unroll
    for (int a = 0; a < 4; a++)
#pragma unroll
        for (int b = 0; b < 4; b++)
#pragma unroll
            for (int cc = 0; cc < 4; cc++) accz[a][b][cc] = 0.f;
    mma_pass(accz, Ah, Al, g);
    store_z(accz, bx0 + g * 128, zxh, zxl);

    // layer-1 h-branch (A-h staged in zhh/zhl)
    float acch[4][4][4];
#pragma unroll
    for (int a = 0; a < 4; a++)
#pragma unroll
        for (int b = 0; b < 4; b++)
#pragma unroll
            for (int cc = 0; cc < 4; cc++) acch[a][b][cc] = 0.f;
    mma_pass(acch, zhh, zhl, 4 + g);
    __syncthreads();    // all warps finished reading A-h (and zxh writes now visible)
    store_z(acch, bh0 + g * 128, zhh, zhl);   // overwrite A-h with z_h
    __syncthreads();    // z_h visible

    // layer-2: y = z_x @ Wx1[g] + z_h @ Wh1[g]   (bias deferred to LSTM)
    float accy[4][4][4];
#pragma unroll
    for (int a = 0; a < 4; a++)
#pragma unroll
        for (int b = 0; b < 4; b++)
#pragma unroll
            for (int cc = 0; cc < 4; cc++) accy[a][b][cc] = 0.f;
    mma_pass(accy, zxh, zxl, 8 + g);
    mma_pass(accy, zhh, zhl, 12 + g);
    gemm_epilogue_y16(accy, g_y16 + g * 128, 512, row0);
}

// ---------------- fused F=512 gather (fp16 y) + LSTM epilogue: one block / node ----------------
__device__ __forceinline__ float sigmoidf_(float v) { return 1.f / (1.f + expf(-v)); }

__global__ void __launch_bounds__(128) k_gather_lstm(
    const float* __restrict__ c,
    const float* __restrict__ bx1, const float* __restrict__ bh1,
    const float* __restrict__ wc, const float* __restrict__ bg,
    float* __restrict__ out)
{
    __shared__ float sG[512];
    int n = blockIdx.x;
    int t = threadIdx.x;
    float sd = g_dis[n];
    float s2 = sd * sd;
    // thread t handles features 4t..4t+3 (8 bytes of fp16)
    uint2 raw = *(const uint2*)(g_y16 + (size_t)n * 512 + t * 4);
    float2 f0 = __half22float2(*(__half2*)&raw.x);
    float2 f1 = __half22float2(*(__half2*)&raw.y);
    float4 acc = make_float4(s2 * f0.x, s2 * f0.y, s2 * f1.x, s2 * f1.y);
    int e0 = g_rowptr[n], e1 = g_rowptr[n + 1];
#pragma unroll 4
    for (int e = e0; e < e1; ++e) {
        int cc = g_ecol[e];
        float nm = g_enorm[e];
        uint2 yr = *(const uint2*)(g_y16 + (size_t)cc * 512 + t * 4);
        float2 y0 = __half22float2(*(__half2*)&yr.x);
        float2 y1 = __half22float2(*(__half2*)&yr.y);
        acc.x = fmaf(nm, y0.x, acc.x); acc.y = fmaf(nm, y0.y, acc.y);
        acc.z = fmaf(nm, y1.x, acc.z); acc.w = fmaf(nm, y1.y, acc.w);
    }
    ((float4*)sG)[t] = acc;
    __syncthreads();
    int f = t;
    int idx = n * HD + f;
    float cv = c[idx];
    float Gi = sG[f]       + bx1[f]       + bh1[f];
    float Gf = sG[128 + f] + bx1[128 + f] + bh1[128 + f];
    float Gc = sG[256 + f] + bx1[256 + f] + bh1[256 + f];
    float Go = sG[384 + f] + bx1[384 + f] + bh1[384 + f];
    float I  = sigmoidf_(Gi + wc[f] * cv + bg[f]);
    float Fg = sigmoidf_(Gf + wc[128 + f] * cv + bg[128 + f]);
    float T  = tanhf(Gc + bg[256 + f]);
    float Cn = Fg * cv + I * T;
    float O  = sigmoidf_(Go + wc[256 + f] * Cn + bg[384 + f]);
    float Hn = O * tanhf(Cn);
    out[idx] = Hn;
    out[(size_t)NNODES * HD + idx] = Cn;
}

// ---------------- launch ----------------
extern "C" void kernel_launch(void* const* d_in, const int* in_sizes, int n_in,
                              void* d_out, int out_size) {
    const float* x   = (const float*)d_in[0];
    const void*  ei  = d_in[1];                 // int32 or int64, detected on device
    const float* w   = (const float*)d_in[2];
    const float* h   = (const float*)d_in[3];
    const float* c   = (const float*)d_in[4];
    const float* Wx0 = (const float*)d_in[5];
    const float* bx0 = (const float*)d_in[6];
    const float* Wx1 = (const float*)d_in[7];
    const float* bx1 = (const float*)d_in[8];
    const float* Wh0 = (const float*)d_in[9];
    const float* bh0 = (const float*)d_in[10];
    const float* Wh1 = (const float*)d_in[11];
    const float* bh1 = (const float*)d_in[12];
    const float* wc  = (const float*)d_in[13];
    const float* bg  = (const float*)d_in[14];
    float* out = (float*)d_out;

    static int smem_set = 0;
    if (!smem_set) {
        cudaFuncSetAttribute(k_mma_fused, cudaFuncAttributeMaxDynamicSharedMemorySize,
                             SMEM_FUSED_BYTES);
        smem_set = 1;
    }

    const int T = 256;
    // prologue: merged init+wprep, then single-kernel edge pipeline
    k_init_wprep<<<256 + (NNODES + T - 1) / T, T>>>((const int*)ei, Wx0, Wh0, Wx1, Wh1);
    k_edges<<<(NEDGES / 4 + T - 1) / T, T>>>(ei, w);

    // fused first props (F=128) for x and h, gather-based
    k_gather_xh<<<(NNODES * 32 + T - 1) / T, T>>>(x, h);

    // fused 2-layer tensor-core GEMM (z stays on-chip, y written fp16)
    dim3 gm((NNODES + 127) / 128, 4);
    k_mma_fused<<<gm, 256, SMEM_FUSED_BYTES>>>(bx0, bh0);

    // fused F=512 gather (fp16) + LSTM epilogue
    k_gather_lstm<<<NNODES, 128>>>(c, bx1, bh1, wc, bg, out);
}